// round 12
// baseline (speedup 1.0000x reference)
#include <cuda_runtime.h>
#include <cuda_bf16.h>
#include <cstdint>

// Problem constants
#define BQ   64
#define NN   128
#define FIN  128
#define HH   512
#define MSGD 512
#define LL   4
#define ROWS (BQ*NN)      // 8192
#define TGT  12

// ---------------- scratch (device globals) ----------------
__device__ float g_h    [ROWS*HH];
__device__ float g_hproj[BQ*LL*NN*MSGD];
__device__ float g_m    [ROWS*MSGD];
__device__ float g_gi   [ROWS*3*HH];
__device__ float g_gh   [ROWS*3*HH];
__device__ float g_mask [ROWS];
__device__ float g_t0   [ROWS*256];
__device__ float g_t1   [ROWS*256];
__device__ float g_gate [ROWS*TGT];
__device__ float g_val  [ROWS*TGT];

// ---------------- bf16x3 helpers ----------------
__device__ __forceinline__ void bsplit1(float x, uint16_t& h, uint16_t& l) {
    __nv_bfloat16 b = __float2bfloat16_rn(x);
    h = __bfloat16_as_ushort(b);
    float r = x - __bfloat162float(b);
    l = __bfloat16_as_ushort(__float2bfloat16_rn(r));
}
__device__ __forceinline__ void bsplit4(float4 v, uint32_t& h0, uint32_t& h1,
                                        uint32_t& l0, uint32_t& l1) {
    uint16_t ha, hb, hc, hd, la, lb, lc, ld;
    bsplit1(v.x, ha, la);
    bsplit1(v.y, hb, lb);
    bsplit1(v.z, hc, lc);
    bsplit1(v.w, hd, ld);
    h0 = (uint32_t)ha | ((uint32_t)hb << 16);
    h1 = (uint32_t)hc | ((uint32_t)hd << 16);
    l0 = (uint32_t)la | ((uint32_t)lb << 16);
    l1 = (uint32_t)lc | ((uint32_t)ld << 16);
}
__device__ __forceinline__ void mma_bf16(float* d, const uint32_t* a, const uint32_t* b) {
    asm volatile(
        "mma.sync.aligned.m16n8k16.row.col.f32.bf16.bf16.f32 "
        "{%0,%1,%2,%3}, {%4,%5,%6,%7}, {%8,%9}, {%0,%1,%2,%3};\n"
        : "+f"(d[0]), "+f"(d[1]), "+f"(d[2]), "+f"(d[3])
        : "r"(a[0]), "r"(a[1]), "r"(a[2]), "r"(a[3]), "r"(b[0]), "r"(b[1]));
}
__device__ __forceinline__ void ldsm_x4(uint32_t& r0, uint32_t& r1, uint32_t& r2, uint32_t& r3,
                                        uint32_t addr) {
    asm volatile("ldmatrix.sync.aligned.m8n8.x4.shared.b16 {%0,%1,%2,%3}, [%4];"
                 : "=r"(r0), "=r"(r1), "=r"(r2), "=r"(r3) : "r"(addr));
}

// ================= BIG kernel: 128x128, BK=32, double-buffered, 2 CTAs/SM =================
#define ROWBB 80                          // 32 bf16 (64B) + 16B pad
#define APLANE_B (128 * ROWBB)            // 10240 B
#define BUFB_B   (4 * APLANE_B)           // Ah,Al,Bh,Bl = 40960 B
#define BIG_SMEM_BYTES (2 * BUFB_B)       // 81920 B

template<bool TRANSB>
__global__ void __launch_bounds__(256, 2)
tgemm_big(const float* __restrict__ A, int lda,
          const float* __restrict__ Bm, int ldb,
          float* __restrict__ C, int ldc,
          int M, int N, int K,
          const float* __restrict__ bias,
          int dv,
          long long aHi, long long aLo,
          long long bHi, long long bLo,
          long long cHi, long long cLo)
{
    extern __shared__ char smc[];

    int z = blockIdx.z;
    int zh = z / dv, zl = z % dv;
    A  += zh*aHi + zl*aLo;
    Bm += zh*bHi + zl*bLo;
    C  += zh*cHi + zl*cLo;

    int tid  = threadIdx.x;
    int lane = tid & 31;
    int wid  = tid >> 5;
    int gid  = lane >> 2;
    int tig  = lane & 3;
    int quad = lane >> 3;
    int rowin= lane & 7;
    int wm   = (wid & 3) * 32;
    int wn   = (wid >> 2) * 64;
    int m0   = blockIdx.y * 128;
    int n0   = blockIdx.x * 128;

    uint32_t sbase = (uint32_t)__cvta_generic_to_shared(smc);

    int aoff = ((quad & 1) * 8 + rowin) * ROWBB + ((quad >> 1) * 16);
    int boff = ((quad >> 1) * 8 + rowin) * ROWBB + ((quad & 1) * 16);

    float4 aS[4], bS[4];
    const float4 f4z = make_float4(0.f, 0.f, 0.f, 0.f);

    auto ldg = [&](int k0) {
#pragma unroll
        for (int i = 0; i < 4; i++) {
            int f = i * 256 + tid;
            int r = f >> 3;                 // 0..127
            int kq = (f & 7) * 4;           // 0..28
            aS[i] = *(const float4*)(A + (size_t)(m0 + r) * lda + k0 + kq);
            if (TRANSB) {
                int n = n0 + r;
                bS[i] = (n < N) ? *(const float4*)(Bm + (size_t)n * ldb + k0 + kq) : f4z;
            } else {
                int rr = f >> 5;            // 0..31 (k)
                int c = (f & 31) * 4;       // n
                int n = n0 + c;
                bS[i] = (n < N) ? *(const float4*)(Bm + (size_t)(k0 + rr) * ldb + n) : f4z;
            }
        }
    };
    auto sts = [&](int buf) {
        char* base = smc + buf * BUFB_B;
#pragma unroll
        for (int i = 0; i < 4; i++) {
            int f = i * 256 + tid;
            int r = f >> 3;
            int kq = (f & 7) * 4;
            uint32_t h0, h1, l0, l1;
            bsplit4(aS[i], h0, h1, l0, l1);
            *(uint2*)(base + r * ROWBB + kq * 2)            = make_uint2(h0, h1);
            *(uint2*)(base + APLANE_B + r * ROWBB + kq * 2) = make_uint2(l0, l1);
            if (TRANSB) {
                bsplit4(bS[i], h0, h1, l0, l1);
                *(uint2*)(base + 2*APLANE_B + r * ROWBB + kq * 2) = make_uint2(h0, h1);
                *(uint2*)(base + 3*APLANE_B + r * ROWBB + kq * 2) = make_uint2(l0, l1);
            } else {
                int rr = f >> 5;
                int c = (f & 31) * 4;
                float bv[4] = {bS[i].x, bS[i].y, bS[i].z, bS[i].w};
#pragma unroll
                for (int q = 0; q < 4; q++) {
                    uint16_t h, l;
                    bsplit1(bv[q], h, l);
                    *(uint16_t*)(base + 2*APLANE_B + (c + q) * ROWBB + rr * 2) = h;
                    *(uint16_t*)(base + 3*APLANE_B + (c + q) * ROWBB + rr * 2) = l;
                }
            }
        }
    };

    float acc[2][8][4];
#pragma unroll
    for (int mt = 0; mt < 2; mt++)
#pragma unroll
        for (int nt = 0; nt < 8; nt++)
#pragma unroll
            for (int q = 0; q < 4; q++) acc[mt][nt][q] = 0.f;

    ldg(0);
    sts(0);
    __syncthreads();

    int cur = 0;
    for (int k0 = 0; k0 < K; k0 += 32) {
        int nxt = k0 + 32;
        if (nxt < K) ldg(nxt);
        uint32_t bb  = sbase + cur * BUFB_B;
        uint32_t ahp = bb + wm * ROWBB + aoff;
        uint32_t alp = ahp + APLANE_B;
        uint32_t bhp = bb + 2*APLANE_B + wn * ROWBB + boff;
        uint32_t blp = bhp + APLANE_B;

#pragma unroll
        for (int kh = 0; kh < 2; kh++) {
            uint32_t ko = kh * 32;       // 16 bf16 = 32 bytes per kk-phase
            uint32_t afh[2][4], afl[2][4], bfh[8][2], bfl[8][2];
            ldsm_x4(afh[0][0], afh[0][1], afh[0][2], afh[0][3], ahp + ko);
            ldsm_x4(afh[1][0], afh[1][1], afh[1][2], afh[1][3], ahp + 16 * ROWBB + ko);
            ldsm_x4(afl[0][0], afl[0][1], afl[0][2], afl[0][3], alp + ko);
            ldsm_x4(afl[1][0], afl[1][1], afl[1][2], afl[1][3], alp + 16 * ROWBB + ko);
#pragma unroll
            for (int p = 0; p < 4; p++) {
                ldsm_x4(bfh[2*p][0], bfh[2*p][1], bfh[2*p+1][0], bfh[2*p+1][1],
                        bhp + p * 16 * ROWBB + ko);
                ldsm_x4(bfl[2*p][0], bfl[2*p][1], bfl[2*p+1][0], bfl[2*p+1][1],
                        blp + p * 16 * ROWBB + ko);
            }
#pragma unroll
            for (int mt = 0; mt < 2; mt++)
#pragma unroll
                for (int nt = 0; nt < 8; nt++) {
                    mma_bf16(acc[mt][nt], afl[mt], bfh[nt]);
                    mma_bf16(acc[mt][nt], afh[mt], bfl[nt]);
                    mma_bf16(acc[mt][nt], afh[mt], bfh[nt]);
                }
        }
        if (nxt < K) {
            sts(cur ^ 1);
            __syncthreads();       // ONE barrier per 32-k tile
            cur ^= 1;
        }
    }

#pragma unroll
    for (int mt = 0; mt < 2; mt++) {
#pragma unroll
        for (int nt = 0; nt < 8; nt++) {
            int row = m0 + wm + mt * 16 + gid;
            int col = n0 + wn + nt * 8 + tig * 2;
            if (col < N) {
#pragma unroll
                for (int half = 0; half < 2; half++) {
                    int r = row + half * 8;
                    float v0 = acc[mt][nt][half * 2 + 0];
                    float v1 = acc[mt][nt][half * 2 + 1];
                    size_t idx = (size_t)r * ldc + col;
                    if (bias) {
                        v0 += __ldg(bias + col);
                        v1 += __ldg(bias + col + 1);
                    }
                    *(float2*)(C + idx) = make_float2(v0, v1);
                }
            }
        }
    }
}

// ================= MLP kernel: 128x64, BK=16, double-buffered static, 2 CTAs/SM =================
#define ROWB 48
#define APLANE (128 * ROWB)       // 6144 B
#define BPLANE_S (64 * ROWB)      // 3072 B
#define BUF_MLP (2 * APLANE + 2 * BPLANE_S)  // 18432 B

template<bool ACC>
__global__ void __launch_bounds__(256, 2)
tgemm_mlp(const float* __restrict__ A, int lda,
          const float* __restrict__ Bm, int ldb,
          float* __restrict__ C, int ldc,
          int M, int N, int K,
          const float* __restrict__ bias, int act)
{
    __shared__ __align__(16) char smc[2 * BUF_MLP];  // 36864 B

    int tid  = threadIdx.x;
    int lane = tid & 31;
    int wid  = tid >> 5;
    int gid  = lane >> 2;
    int tig  = lane & 3;
    int quad = lane >> 3;
    int rowin= lane & 7;
    int wm   = (wid & 3) * 32;
    int wn   = (wid >> 2) * 32;
    int m0   = blockIdx.y * 128;
    int n0   = blockIdx.x * 64;

    uint32_t sbase = (uint32_t)__cvta_generic_to_shared(smc);
    int aoff = ((quad & 1) * 8 + rowin) * ROWB + ((quad >> 1) * 16);
    int boff = ((quad >> 1) * 8 + rowin) * ROWB + ((quad & 1) * 16);

    float4 aS[2], bS;
    const float4 f4z = make_float4(0.f, 0.f, 0.f, 0.f);

    auto ldg = [&](int k0) {
#pragma unroll
        for (int i = 0; i < 2; i++) {
            int f = i * 256 + tid;
            int r = f >> 2;
            int kq = (f & 3) * 4;
            aS[i] = *(const float4*)(A + (size_t)(m0 + r) * lda + k0 + kq);
        }
        int r = tid >> 2;
        int kq = (tid & 3) * 4;
        int n = n0 + r;
        bS = (n < N) ? *(const float4*)(Bm + (size_t)n * ldb + k0 + kq) : f4z;
    };
    auto sts = [&](int buf) {
        char* base = smc + buf * BUF_MLP;
#pragma unroll
        for (int i = 0; i < 2; i++) {
            int f = i * 256 + tid;
            int r = f >> 2;
            int kq = (f & 3) * 4;
            uint32_t h0, h1, l0, l1;
            bsplit4(aS[i], h0, h1, l0, l1);
            *(uint2*)(base + r * ROWB + kq * 2)          = make_uint2(h0, h1);
            *(uint2*)(base + APLANE + r * ROWB + kq * 2) = make_uint2(l0, l1);
        }
        {
            int r = tid >> 2;
            int kq = (tid & 3) * 4;
            uint32_t h0, h1, l0, l1;
            bsplit4(bS, h0, h1, l0, l1);
            *(uint2*)(base + 2*APLANE + r * ROWB + kq * 2)            = make_uint2(h0, h1);
            *(uint2*)(base + 2*APLANE + BPLANE_S + r * ROWB + kq * 2) = make_uint2(l0, l1);
        }
    };

    float acc[2][4][4];
#pragma unroll
    for (int mt = 0; mt < 2; mt++)
#pragma unroll
        for (int nt = 0; nt < 4; nt++)
#pragma unroll
            for (int q = 0; q < 4; q++) acc[mt][nt][q] = 0.f;

    ldg(0);
    sts(0);
    __syncthreads();

    int cur = 0;
    for (int k0 = 0; k0 < K; k0 += 16) {
        int nxt = k0 + 16;
        if (nxt < K) ldg(nxt);
        uint32_t bb  = sbase + cur * BUF_MLP;
        uint32_t ahp = bb + wm * ROWB + aoff;
        uint32_t alp = ahp + APLANE;
        uint32_t bhp = bb + 2*APLANE + wn * ROWB + boff;
        uint32_t blp = bhp + BPLANE_S;

        uint32_t afh[2][4], afl[2][4], bfh[4][2], bfl[4][2];
        ldsm_x4(afh[0][0], afh[0][1], afh[0][2], afh[0][3], ahp);
        ldsm_x4(afh[1][0], afh[1][1], afh[1][2], afh[1][3], ahp + 16 * ROWB);
        ldsm_x4(afl[0][0], afl[0][1], afl[0][2], afl[0][3], alp);
        ldsm_x4(afl[1][0], afl[1][1], afl[1][2], afl[1][3], alp + 16 * ROWB);
#pragma unroll
        for (int p = 0; p < 2; p++) {
            ldsm_x4(bfh[2*p][0], bfh[2*p][1], bfh[2*p+1][0], bfh[2*p+1][1], bhp + p * 16 * ROWB);
            ldsm_x4(bfl[2*p][0], bfl[2*p][1], bfl[2*p+1][0], bfl[2*p+1][1], blp + p * 16 * ROWB);
        }
#pragma unroll
        for (int mt = 0; mt < 2; mt++)
#pragma unroll
            for (int nt = 0; nt < 4; nt++) {
                mma_bf16(acc[mt][nt], afl[mt], bfh[nt]);
                mma_bf16(acc[mt][nt], afh[mt], bfl[nt]);
                mma_bf16(acc[mt][nt], afh[mt], bfh[nt]);
            }
        if (nxt < K) {
            sts(cur ^ 1);
            __syncthreads();
            cur ^= 1;
        }
    }

#pragma unroll
    for (int mt = 0; mt < 2; mt++) {
#pragma unroll
        for (int nt = 0; nt < 4; nt++) {
            int row = m0 + wm + mt * 16 + gid;
            int col = n0 + wn + nt * 8 + tig * 2;
            if (col < N) {
#pragma unroll
                for (int half = 0; half < 2; half++) {
                    int r = row + half * 8;
                    float v0 = acc[mt][nt][half * 2 + 0];
                    float v1 = acc[mt][nt][half * 2 + 1];
                    size_t idx = (size_t)r * ldc + col;
                    if (ACC) {
                        float2 old = *(const float2*)(C + idx);
                        v0 += old.x; v1 += old.y;
                    }
                    if (bias) {
                        v0 += __ldg(bias + col);
                        v1 += __ldg(bias + col + 1);
                    }
                    if (act == 1) { v0 = fmaxf(v0, 0.f); v1 = fmaxf(v1, 0.f); }
                    else if (act == 2) {
                        v0 = 1.f / (1.f + __expf(-v0));
                        v1 = 1.f / (1.f + __expf(-v1));
                    }
                    *(float2*)(C + idx) = make_float2(v0, v1);
                }
            }
        }
    }
}

// ---------------- elementwise kernels ----------------
__global__ void init_kernel(const float* __restrict__ h_in,
                            float* __restrict__ h, float* __restrict__ mask)
{
    int row = blockIdx.x;
    int t = threadIdx.x;   // 128
    float v = h_in[(size_t)row * FIN + t];
    float s = fabsf(v);
#pragma unroll
    for (int o = 16; o; o >>= 1) s += __shfl_xor_sync(0xffffffffu, s, o);
    __shared__ float ws[4];
    if ((t & 31) == 0) ws[t >> 5] = s;
    __syncthreads();
    if (t == 0) {
        float tot = ws[0] + ws[1] + ws[2] + ws[3];
        mask[row] = (tot > 0.f) ? 1.f : 0.f;
    }
    float* hr = h + (size_t)row * HH;
    hr[t]         = v;
    hr[t + 128]   = 0.f;
    hr[t + 256]   = 0.f;
    hr[t + 384]   = 0.f;
}

__global__ void agg_kernel(const float* __restrict__ e,
                           const float* __restrict__ hproj,
                           float* __restrict__ m)
{
    int row = blockIdx.x;          // b*128 + v
    int b = row >> 7;
    int t = threadIdx.x;           // 128
    __shared__ int cnt;
    __shared__ int widx[NN];
    __shared__ int wlab[NN];
    if (t == 0) cnt = 0;
    __syncthreads();
    float ev = e[(size_t)row * NN + t];
    int lab = (int)(ev + 0.5f);
    if (lab >= 1) {
        int p = atomicAdd(&cnt, 1);
        widx[p] = t;
        wlab[p] = lab - 1;
    }
    __syncthreads();
    float a0 = 0.f, a1 = 0.f, a2 = 0.f, a3 = 0.f;
    int n = cnt;
    const float* hb = hproj + (size_t)b * LL * NN * MSGD;
    for (int i = 0; i < n; i++) {
        const float* src = hb + ((size_t)wlab[i] * NN + widx[i]) * MSGD;
        a0 += __ldg(src + t);
        a1 += __ldg(src + t + 128);
        a2 += __ldg(src + t + 256);
        a3 += __ldg(src + t + 384);
    }
    float* o = m + (size_t)row * MSGD;
    o[t]       = a0;
    o[t + 128] = a1;
    o[t + 256] = a2;
    o[t + 384] = a3;
}

__global__ void gru_kernel(float* __restrict__ h,
                           const float* __restrict__ gi,
                           const float* __restrict__ gh,
                           const float* __restrict__ mask)
{
    int row = blockIdx.x;
    int t = threadIdx.x;   // 128
    float mk = mask[row];
    const float* gir = gi + (size_t)row * 3 * HH;
    const float* ghr = gh + (size_t)row * 3 * HH;
    float* hr = h + (size_t)row * HH;
#pragma unroll
    for (int j = 0; j < 4; j++) {
        int idx = t + j * 128;
        float ir = gir[idx], iz = gir[idx + HH], in_ = gir[idx + 2 * HH];
        float hrv = ghr[idx], hz = ghr[idx + HH], hn = ghr[idx + 2 * HH];
        float r  = 1.f / (1.f + __expf(-(ir + hrv)));
        float z  = 1.f / (1.f + __expf(-(iz + hz)));
        float nn = tanhf(in_ + r * hn);
        float ho = hr[idx];
        hr[idx] = ((1.f - z) * nn + z * ho) * mk;
    }
}

__global__ void reduce_kernel(const float* __restrict__ gate,
                              const float* __restrict__ val,
                              const float* __restrict__ mask,
                              float* __restrict__ out)
{
    __shared__ float sm[TGT][NN];
    int b = blockIdx.x;
    int t = threadIdx.x;   // 128
    int row = b * NN + t;
    float mk = mask[row];
#pragma unroll
    for (int j = 0; j < TGT; j++)
        sm[j][t] = gate[(size_t)row * TGT + j] * val[(size_t)row * TGT + j] * mk;
    __syncthreads();
    for (int s = 64; s > 0; s >>= 1) {
        if (t < s) {
#pragma unroll
            for (int j = 0; j < TGT; j++) sm[j][t] += sm[j][t + s];
        }
        __syncthreads();
    }
    if (t < TGT) out[b * TGT + t] = sm[t][0];
}

// ---------------- host side ----------------
static void gemm_big_l(const float* A, int lda, const float* B, int ldb,
                       float* C, int ldc, int M, int N, int K,
                       const float* bias, bool transb,
                       int batches = 1, int dv = 1,
                       long long aHi = 0, long long aLo = 0,
                       long long bHi = 0, long long bLo = 0,
                       long long cHi = 0, long long cLo = 0)
{
    dim3 grid((N + 127) / 128, M / 128, batches);
    if (transb)
        tgemm_big<true ><<<grid, 256, BIG_SMEM_BYTES>>>(A, lda, B, ldb, C, ldc, M, N, K, bias, dv, aHi, aLo, bHi, bLo, cHi, cLo);
    else
        tgemm_big<false><<<grid, 256, BIG_SMEM_BYTES>>>(A, lda, B, ldb, C, ldc, M, N, K, bias, dv, aHi, aLo, bHi, bLo, cHi, cLo);
}

static void gemm_mlp_l(const float* A, int lda, const float* B, int ldb,
                       float* C, int ldc, int M, int N, int K,
                       const float* bias, int act, bool acc)
{
    dim3 grid((N + 63) / 64, M / 128, 1);
    if (acc) tgemm_mlp<true ><<<grid, 256>>>(A, lda, B, ldb, C, ldc, M, N, K, bias, act);
    else     tgemm_mlp<false><<<grid, 256>>>(A, lda, B, ldb, C, ldc, M, N, K, bias, act);
}

extern "C" void kernel_launch(void* const* d_in, const int* in_sizes, int n_in,
                              void* d_out, int out_size)
{
    const float* h_in  = (const float*)d_in[1];
    const float* e     = (const float*)d_in[2];
    const float* Amat  = (const float*)d_in[3];
    const float* Wih   = (const float*)d_in[4];
    const float* Whh   = (const float*)d_in[5];
    const float* bih   = (const float*)d_in[6];
    const float* bhh   = (const float*)d_in[7];

    cudaFuncSetAttribute(tgemm_big<true >, cudaFuncAttributeMaxDynamicSharedMemorySize, BIG_SMEM_BYTES);
    cudaFuncSetAttribute(tgemm_big<false>, cudaFuncAttributeMaxDynamicSharedMemorySize, BIG_SMEM_BYTES);

    const float *r1W[4], *r1b[4], *r2W[4], *r2b[4];
    if (in_sizes[10] == 65536) {
        for (int i = 0; i < 4; i++) {
            r1W[i] = (const float*)d_in[8 + 4 * i];
            r1b[i] = (const float*)d_in[9 + 4 * i];
            r2W[i] = (const float*)d_in[10 + 4 * i];
            r2b[i] = (const float*)d_in[11 + 4 * i];
        }
    } else {
        for (int i = 0; i < 4; i++) {
            r1W[i] = (const float*)d_in[8 + 2 * i];
            r1b[i] = (const float*)d_in[9 + 2 * i];
            r2W[i] = (const float*)d_in[16 + 2 * i];
            r2b[i] = (const float*)d_in[17 + 2 * i];
        }
    }
    float* out = (float*)d_out;

    float *h_, *hproj, *m_, *gi, *gh, *mask, *t0, *t1, *gate, *val;
    cudaGetSymbolAddress((void**)&h_,    g_h);
    cudaGetSymbolAddress((void**)&hproj, g_hproj);
    cudaGetSymbolAddress((void**)&m_,    g_m);
    cudaGetSymbolAddress((void**)&gi,    g_gi);
    cudaGetSymbolAddress((void**)&gh,    g_gh);
    cudaGetSymbolAddress((void**)&mask,  g_mask);
    cudaGetSymbolAddress((void**)&t0,    g_t0);
    cudaGetSymbolAddress((void**)&t1,    g_t1);
    cudaGetSymbolAddress((void**)&gate,  g_gate);
    cudaGetSymbolAddress((void**)&val,   g_val);

    init_kernel<<<ROWS, 128>>>(h_in, h_, mask);

    for (int step = 0; step < 4; step++) {
        // hproj[b,l] = h[b] @ A[l]   (256 batched 128x512x512)
        gemm_big_l(h_, HH, Amat, MSGD, hproj, MSGD,
                   NN, MSGD, HH, nullptr, /*transb=*/false,
                   /*batches=*/BQ * LL, /*dv=*/LL,
                   (long long)NN * HH, 0,
                   0, (long long)HH * MSGD,
                   (long long)LL * NN * MSGD, (long long)NN * MSGD);

        agg_kernel<<<ROWS, 128>>>(e, hproj, m_);

        gemm_big_l(m_, MSGD, Wih, MSGD, gi, 3 * HH, ROWS, 3 * HH, MSGD, bih, true);
        gemm_big_l(h_, HH,   Whh, HH,   gh, 3 * HH, ROWS, 3 * HH, HH,   bhh, true);

        gru_kernel<<<ROWS, 128>>>(h_, gi, gh, mask);
    }

    // gate chain: relu(concat(h,h0) @ W0^T + b0) as two GEMMs (h0 tail = h_in pad)
    gemm_mlp_l(h_,   HH,  r1W[0],      2 * HH, t0, 128, ROWS, 128, HH,  nullptr, 0, false);
    gemm_mlp_l(h_in, FIN, r1W[0] + HH, 2 * HH, t0, 128, ROWS, 128, FIN, r1b[0],  1, true);
    gemm_mlp_l(t0, 128, r1W[1], 128, t1, 256, ROWS, 256, 128, r1b[1], 1, false);
    gemm_mlp_l(t1, 256, r1W[2], 256, t0, 128, ROWS, 128, 256, r1b[2], 1, false);
    gemm_mlp_l(t0, 128, r1W[3], 128, gate, TGT, ROWS, TGT, 128, r1b[3], 2, false);

    // val chain
    gemm_mlp_l(h_, HH,  r2W[0], HH,  t0, 128, ROWS, 128, HH,  r2b[0], 1, false);
    gemm_mlp_l(t0, 128, r2W[1], 128, t1, 256, ROWS, 256, 128, r2b[1], 1, false);
    gemm_mlp_l(t1, 256, r2W[2], 256, t0, 128, ROWS, 128, 256, r2b[2], 1, false);
    gemm_mlp_l(t0, 128, r2W[3], 128, val, TGT, ROWS, TGT, 128, r2b[3], 0, false);

    reduce_kernel<<<BQ, 128>>>(gate, val, mask, out);
}

// round 13
// speedup vs baseline: 1.4226x; 1.4226x over previous
#include <cuda_runtime.h>
#include <cuda_bf16.h>
#include <cstdint>

// Problem constants
#define BQ   64
#define NN   128
#define FIN  128
#define HH   512
#define MSGD 512
#define LL   4
#define ROWS (BQ*NN)      // 8192
#define TGT  12

// ---------------- scratch (device globals) ----------------
__device__ float g_h    [ROWS*HH];
__device__ float g_hproj[BQ*LL*NN*MSGD];
__device__ float g_m    [ROWS*MSGD];
__device__ float g_gi   [ROWS*3*HH];
__device__ float g_gh   [ROWS*3*HH];
__device__ float g_mask [ROWS];
__device__ float g_t0   [ROWS*256];
__device__ float g_t1   [ROWS*256];
__device__ float g_gate [ROWS*TGT];
__device__ float g_val  [ROWS*TGT];
__device__ float g_AT   [LL*HH*MSGD];   // Amat transposed: [l][m][k]

// ---------------- bf16x3 helpers ----------------
__device__ __forceinline__ void bsplit1(float x, uint16_t& h, uint16_t& l) {
    __nv_bfloat16 b = __float2bfloat16_rn(x);
    h = __bfloat16_as_ushort(b);
    float r = x - __bfloat162float(b);
    l = __bfloat16_as_ushort(__float2bfloat16_rn(r));
}
__device__ __forceinline__ void bsplit4(float4 v, uint32_t& h0, uint32_t& h1,
                                        uint32_t& l0, uint32_t& l1) {
    uint16_t ha, hb, hc, hd, la, lb, lc, ld;
    bsplit1(v.x, ha, la);
    bsplit1(v.y, hb, lb);
    bsplit1(v.z, hc, lc);
    bsplit1(v.w, hd, ld);
    h0 = (uint32_t)ha | ((uint32_t)hb << 16);
    h1 = (uint32_t)hc | ((uint32_t)hd << 16);
    l0 = (uint32_t)la | ((uint32_t)lb << 16);
    l1 = (uint32_t)lc | ((uint32_t)ld << 16);
}
__device__ __forceinline__ void mma_bf16(float* d, const uint32_t* a, const uint32_t* b) {
    asm volatile(
        "mma.sync.aligned.m16n8k16.row.col.f32.bf16.bf16.f32 "
        "{%0,%1,%2,%3}, {%4,%5,%6,%7}, {%8,%9}, {%0,%1,%2,%3};\n"
        : "+f"(d[0]), "+f"(d[1]), "+f"(d[2]), "+f"(d[3])
        : "r"(a[0]), "r"(a[1]), "r"(a[2]), "r"(a[3]), "r"(b[0]), "r"(b[1]));
}
__device__ __forceinline__ void ldsm_x4(uint32_t& r0, uint32_t& r1, uint32_t& r2, uint32_t& r3,
                                        uint32_t addr) {
    asm volatile("ldmatrix.sync.aligned.m8n8.x4.shared.b16 {%0,%1,%2,%3}, [%4];"
                 : "=r"(r0), "=r"(r1), "=r"(r2), "=r"(r3) : "r"(addr));
}

#define ROWB 48            // bytes per smem row: 16 bf16 (32B) + 16B pad

// ================= BIG kernel: 128x128, BK=16, double-buffered, 2 CTAs/SM (R11) ==========
#define APLANE (128 * ROWB)              // 6144 B
#define BUFB   (4 * APLANE)              // Ah,Al,Bh,Bl = 24576 B
#define BIG_SMEM_BYTES (2 * BUFB)        // 49152 B

__global__ void __launch_bounds__(256, 2)
tgemm_big(const float* __restrict__ A, int lda,
          const float* __restrict__ Bm, int ldb,
          float* __restrict__ C, int ldc,
          int M, int N, int K,
          const float* __restrict__ bias,
          int dv,
          long long aHi, long long aLo,
          long long bHi, long long bLo,
          long long cHi, long long cLo)
{
    extern __shared__ char smc[];

    int z = blockIdx.z;
    int zh = z / dv, zl = z % dv;
    A  += zh*aHi + zl*aLo;
    Bm += zh*bHi + zl*bLo;
    C  += zh*cHi + zl*cLo;

    int tid  = threadIdx.x;
    int lane = tid & 31;
    int wid  = tid >> 5;
    int gid  = lane >> 2;
    int tig  = lane & 3;
    int quad = lane >> 3;
    int rowin= lane & 7;
    int wm   = (wid & 3) * 32;
    int wn   = (wid >> 2) * 64;
    int m0   = blockIdx.y * 128;
    int n0   = blockIdx.x * 128;

    uint32_t sbase = (uint32_t)__cvta_generic_to_shared(smc);

    int aoff = ((quad & 1) * 8 + rowin) * ROWB + ((quad >> 1) * 16);
    int boff = ((quad >> 1) * 8 + rowin) * ROWB + ((quad & 1) * 16);

    float4 aS[2], bS[2];
    const float4 f4z = make_float4(0.f, 0.f, 0.f, 0.f);

    auto ldg = [&](int k0) {
#pragma unroll
        for (int i = 0; i < 2; i++) {
            int f = i * 256 + tid;
            int r = f >> 2;
            int kq = (f & 3) * 4;
            aS[i] = *(const float4*)(A + (size_t)(m0 + r) * lda + k0 + kq);
            int n = n0 + r;
            bS[i] = (n < N) ? *(const float4*)(Bm + (size_t)n * ldb + k0 + kq) : f4z;
        }
    };
    auto sts = [&](int buf) {
        char* base = smc + buf * BUFB;
#pragma unroll
        for (int i = 0; i < 2; i++) {
            int f = i * 256 + tid;
            int r = f >> 2;
            int kq = (f & 3) * 4;
            uint32_t h0, h1, l0, l1;
            bsplit4(aS[i], h0, h1, l0, l1);
            *(uint2*)(base + r * ROWB + kq * 2)          = make_uint2(h0, h1);
            *(uint2*)(base + APLANE + r * ROWB + kq * 2) = make_uint2(l0, l1);
            bsplit4(bS[i], h0, h1, l0, l1);
            *(uint2*)(base + 2*APLANE + r * ROWB + kq * 2) = make_uint2(h0, h1);
            *(uint2*)(base + 3*APLANE + r * ROWB + kq * 2) = make_uint2(l0, l1);
        }
    };

    float acc[2][8][4];
#pragma unroll
    for (int mt = 0; mt < 2; mt++)
#pragma unroll
        for (int nt = 0; nt < 8; nt++)
#pragma unroll
            for (int q = 0; q < 4; q++) acc[mt][nt][q] = 0.f;

    ldg(0);
    sts(0);
    __syncthreads();

    int cur = 0;
    for (int k0 = 0; k0 < K; k0 += 16) {
        int nxt = k0 + 16;
        if (nxt < K) ldg(nxt);
        uint32_t bb  = sbase + cur * BUFB;
        uint32_t ahp = bb + wm * ROWB + aoff;
        uint32_t alp = ahp + APLANE;
        uint32_t bhp = bb + 2*APLANE + wn * ROWB + boff;
        uint32_t blp = bhp + APLANE;

        uint32_t afh[2][4], afl[2][4], bfh[8][2], bfl[8][2];
        ldsm_x4(afh[0][0], afh[0][1], afh[0][2], afh[0][3], ahp);
        ldsm_x4(afh[1][0], afh[1][1], afh[1][2], afh[1][3], ahp + 16 * ROWB);
        ldsm_x4(afl[0][0], afl[0][1], afl[0][2], afl[0][3], alp);
        ldsm_x4(afl[1][0], afl[1][1], afl[1][2], afl[1][3], alp + 16 * ROWB);
#pragma unroll
        for (int p = 0; p < 4; p++) {
            ldsm_x4(bfh[2*p][0], bfh[2*p][1], bfh[2*p+1][0], bfh[2*p+1][1], bhp + p * 16 * ROWB);
            ldsm_x4(bfl[2*p][0], bfl[2*p][1], bfl[2*p+1][0], bfl[2*p+1][1], blp + p * 16 * ROWB);
        }
#pragma unroll
        for (int mt = 0; mt < 2; mt++)
#pragma unroll
            for (int nt = 0; nt < 8; nt++) {
                mma_bf16(acc[mt][nt], afl[mt], bfh[nt]);
                mma_bf16(acc[mt][nt], afh[mt], bfl[nt]);
                mma_bf16(acc[mt][nt], afh[mt], bfh[nt]);
            }
        if (nxt < K) {
            sts(cur ^ 1);
            __syncthreads();       // ONE barrier per tile
            cur ^= 1;
        }
    }

#pragma unroll
    for (int mt = 0; mt < 2; mt++) {
#pragma unroll
        for (int nt = 0; nt < 8; nt++) {
            int row = m0 + wm + mt * 16 + gid;
            int col = n0 + wn + nt * 8 + tig * 2;
            if (col < N) {
#pragma unroll
                for (int half = 0; half < 2; half++) {
                    int r = row + half * 8;
                    float v0 = acc[mt][nt][half * 2 + 0];
                    float v1 = acc[mt][nt][half * 2 + 1];
                    size_t idx = (size_t)r * ldc + col;
                    if (bias) {
                        v0 += __ldg(bias + col);
                        v1 += __ldg(bias + col + 1);
                    }
                    *(float2*)(C + idx) = make_float2(v0, v1);
                }
            }
        }
    }
}

// ================= MLP kernel: 128x64, static smem, 2 CTAs/SM (R11 config) =================
#define BPLANE_S (64 * ROWB)   // 3072 B

template<bool ACC>
__global__ void __launch_bounds__(256, 2)
tgemm_mlp(const float* __restrict__ A, int lda,
          const float* __restrict__ Bm, int ldb,
          float* __restrict__ C, int ldc,
          int M, int N, int K,
          const float* __restrict__ bias, int act)
{
    __shared__ __align__(16) char smc[2 * APLANE + 2 * BPLANE_S];  // 18432 B

    int tid  = threadIdx.x;
    int lane = tid & 31;
    int wid  = tid >> 5;
    int gid  = lane >> 2;
    int tig  = lane & 3;
    int quad = lane >> 3;
    int rowin= lane & 7;
    int wm   = (wid & 3) * 32;
    int wn   = (wid >> 2) * 32;
    int m0   = blockIdx.y * 128;
    int n0   = blockIdx.x * 64;

    uint32_t sbase = (uint32_t)__cvta_generic_to_shared(smc);
    int aoff = ((quad & 1) * 8 + rowin) * ROWB + ((quad >> 1) * 16);
    int boff = ((quad >> 1) * 8 + rowin) * ROWB + ((quad & 1) * 16);

    float4 aS[2], bS;
    const float4 f4z = make_float4(0.f, 0.f, 0.f, 0.f);

    auto ldg = [&](int k0) {
#pragma unroll
        for (int i = 0; i < 2; i++) {
            int f = i * 256 + tid;
            int r = f >> 2;
            int kq = (f & 3) * 4;
            aS[i] = *(const float4*)(A + (size_t)(m0 + r) * lda + k0 + kq);
        }
        int r = tid >> 2;
        int kq = (tid & 3) * 4;
        int n = n0 + r;
        bS = (n < N) ? *(const float4*)(Bm + (size_t)n * ldb + k0 + kq) : f4z;
    };
    auto sts = [&]() {
#pragma unroll
        for (int i = 0; i < 2; i++) {
            int f = i * 256 + tid;
            int r = f >> 2;
            int kq = (f & 3) * 4;
            uint32_t h0, h1, l0, l1;
            bsplit4(aS[i], h0, h1, l0, l1);
            *(uint2*)(smc + r * ROWB + kq * 2)          = make_uint2(h0, h1);
            *(uint2*)(smc + APLANE + r * ROWB + kq * 2) = make_uint2(l0, l1);
        }
        {
            int r = tid >> 2;
            int kq = (tid & 3) * 4;
            uint32_t h0, h1, l0, l1;
            bsplit4(bS, h0, h1, l0, l1);
            *(uint2*)(smc + 2*APLANE + r * ROWB + kq * 2)            = make_uint2(h0, h1);
            *(uint2*)(smc + 2*APLANE + BPLANE_S + r * ROWB + kq * 2) = make_uint2(l0, l1);
        }
    };

    float acc[2][4][4];
#pragma unroll
    for (int mt = 0; mt < 2; mt++)
#pragma unroll
        for (int nt = 0; nt < 4; nt++)
#pragma unroll
            for (int q = 0; q < 4; q++) acc[mt][nt][q] = 0.f;

    ldg(0);
    sts();
    __syncthreads();

    for (int k0 = 0; k0 < K; k0 += 16) {
        int nxt = k0 + 16;
        if (nxt < K) ldg(nxt);
        uint32_t ahp = sbase + wm * ROWB + aoff;
        uint32_t alp = ahp + APLANE;
        uint32_t bhp = sbase + 2*APLANE + wn * ROWB + boff;
        uint32_t blp = bhp + BPLANE_S;

        uint32_t afh[2][4], afl[2][4], bfh[4][2], bfl[4][2];
        ldsm_x4(afh[0][0], afh[0][1], afh[0][2], afh[0][3], ahp);
        ldsm_x4(afh[1][0], afh[1][1], afh[1][2], afh[1][3], ahp + 16 * ROWB);
        ldsm_x4(afl[0][0], afl[0][1], afl[0][2], afl[0][3], alp);
        ldsm_x4(afl[1][0], afl[1][1], afl[1][2], afl[1][3], alp + 16 * ROWB);
#pragma unroll
        for (int p = 0; p < 2; p++) {
            ldsm_x4(bfh[2*p][0], bfh[2*p][1], bfh[2*p+1][0], bfh[2*p+1][1], bhp + p * 16 * ROWB);
            ldsm_x4(bfl[2*p][0], bfl[2*p][1], bfl[2*p+1][0], bfl[2*p+1][1], blp + p * 16 * ROWB);
        }
#pragma unroll
        for (int mt = 0; mt < 2; mt++)
#pragma unroll
            for (int nt = 0; nt < 4; nt++) {
                mma_bf16(acc[mt][nt], afl[mt], bfh[nt]);
                mma_bf16(acc[mt][nt], afh[mt], bfl[nt]);
                mma_bf16(acc[mt][nt], afh[mt], bfh[nt]);
            }
        if (nxt < K) {
            __syncthreads();
            sts();
            __syncthreads();
        }
    }

#pragma unroll
    for (int mt = 0; mt < 2; mt++) {
#pragma unroll
        for (int nt = 0; nt < 4; nt++) {
            int row = m0 + wm + mt * 16 + gid;
            int col = n0 + wn + nt * 8 + tig * 2;
            if (col < N) {
#pragma unroll
                for (int half = 0; half < 2; half++) {
                    int r = row + half * 8;
                    float v0 = acc[mt][nt][half * 2 + 0];
                    float v1 = acc[mt][nt][half * 2 + 1];
                    size_t idx = (size_t)r * ldc + col;
                    if (ACC) {
                        float2 old = *(const float2*)(C + idx);
                        v0 += old.x; v1 += old.y;
                    }
                    if (bias) {
                        v0 += __ldg(bias + col);
                        v1 += __ldg(bias + col + 1);
                    }
                    if (act == 1) { v0 = fmaxf(v0, 0.f); v1 = fmaxf(v1, 0.f); }
                    else if (act == 2) {
                        v0 = 1.f / (1.f + __expf(-v0));
                        v1 = 1.f / (1.f + __expf(-v1));
                    }
                    *(float2*)(C + idx) = make_float2(v0, v1);
                }
            }
        }
    }
}

// ---------------- Amat transpose: [l][k][m] -> [l][m][k] ----------------
__global__ void transposeA_kernel(const float* __restrict__ Amat, float* __restrict__ AT)
{
    __shared__ float tile[32][33];
    int l = blockIdx.z;
    int kb = blockIdx.x * 32;     // k block
    int mb = blockIdx.y * 32;     // m block
    const float* src = Amat + (size_t)l * HH * MSGD;
    float* dst = AT + (size_t)l * HH * MSGD;
    int tx = threadIdx.x;         // 32
    int ty = threadIdx.y;         // 8
#pragma unroll
    for (int i = 0; i < 4; i++) {
        int k = kb + ty + i * 8;
        tile[ty + i * 8][tx] = src[(size_t)k * MSGD + mb + tx];
    }
    __syncthreads();
#pragma unroll
    for (int i = 0; i < 4; i++) {
        int m = mb + ty + i * 8;
        dst[(size_t)m * HH + kb + tx] = tile[tx][ty + i * 8];
    }
}

// ---------------- elementwise kernels ----------------
__global__ void init_kernel(const float* __restrict__ h_in,
                            float* __restrict__ h, float* __restrict__ mask)
{
    int row = blockIdx.x;
    int t = threadIdx.x;   // 128
    float v = h_in[(size_t)row * FIN + t];
    float s = fabsf(v);
#pragma unroll
    for (int o = 16; o; o >>= 1) s += __shfl_xor_sync(0xffffffffu, s, o);
    __shared__ float ws[4];
    if ((t & 31) == 0) ws[t >> 5] = s;
    __syncthreads();
    if (t == 0) {
        float tot = ws[0] + ws[1] + ws[2] + ws[3];
        mask[row] = (tot > 0.f) ? 1.f : 0.f;
    }
    float* hr = h + (size_t)row * HH;
    hr[t]         = v;
    hr[t + 128]   = 0.f;
    hr[t + 256]   = 0.f;
    hr[t + 384]   = 0.f;
}

__global__ void agg_kernel(const float* __restrict__ e,
                           const float* __restrict__ hproj,
                           float* __restrict__ m)
{
    int row = blockIdx.x;          // b*128 + v
    int b = row >> 7;
    int t = threadIdx.x;           // 128
    __shared__ int cnt;
    __shared__ int widx[NN];
    __shared__ int wlab[NN];
    if (t == 0) cnt = 0;
    __syncthreads();
    float ev = e[(size_t)row * NN + t];
    int lab = (int)(ev + 0.5f);
    if (lab >= 1) {
        int p = atomicAdd(&cnt, 1);
        widx[p] = t;
        wlab[p] = lab - 1;
    }
    __syncthreads();
    float a0 = 0.f, a1 = 0.f, a2 = 0.f, a3 = 0.f;
    int n = cnt;
    const float* hb = hproj + (size_t)b * LL * NN * MSGD;
    for (int i = 0; i < n; i++) {
        const float* src = hb + ((size_t)wlab[i] * NN + widx[i]) * MSGD;
        a0 += __ldg(src + t);
        a1 += __ldg(src + t + 128);
        a2 += __ldg(src + t + 256);
        a3 += __ldg(src + t + 384);
    }
    float* o = m + (size_t)row * MSGD;
    o[t]       = a0;
    o[t + 128] = a1;
    o[t + 256] = a2;
    o[t + 384] = a3;
}

__global__ void gru_kernel(float* __restrict__ h,
                           const float* __restrict__ gi,
                           const float* __restrict__ gh,
                           const float* __restrict__ mask)
{
    int row = blockIdx.x;
    int t = threadIdx.x;   // 128
    float mk = mask[row];
    const float* gir = gi + (size_t)row * 3 * HH;
    const float* ghr = gh + (size_t)row * 3 * HH;
    float* hr = h + (size_t)row * HH;
#pragma unroll
    for (int j = 0; j < 4; j++) {
        int idx = t + j * 128;
        float ir = gir[idx], iz = gir[idx + HH], in_ = gir[idx + 2 * HH];
        float hrv = ghr[idx], hz = ghr[idx + HH], hn = ghr[idx + 2 * HH];
        float r  = 1.f / (1.f + __expf(-(ir + hrv)));
        float z  = 1.f / (1.f + __expf(-(iz + hz)));
        float nn = tanhf(in_ + r * hn);
        float ho = hr[idx];
        hr[idx] = ((1.f - z) * nn + z * ho) * mk;
    }
}

__global__ void reduce_kernel(const float* __restrict__ gate,
                              const float* __restrict__ val,
                              const float* __restrict__ mask,
                              float* __restrict__ out)
{
    __shared__ float sm[TGT][NN];
    int b = blockIdx.x;
    int t = threadIdx.x;   // 128
    int row = b * NN + t;
    float mk = mask[row];
#pragma unroll
    for (int j = 0; j < TGT; j++)
        sm[j][t] = gate[(size_t)row * TGT + j] * val[(size_t)row * TGT + j] * mk;
    __syncthreads();
    for (int s = 64; s > 0; s >>= 1) {
        if (t < s) {
#pragma unroll
            for (int j = 0; j < TGT; j++) sm[j][t] += sm[j][t + s];
        }
        __syncthreads();
    }
    if (t < TGT) out[b * TGT + t] = sm[t][0];
}

// ---------------- host side ----------------
static void gemm_big_l(const float* A, int lda, const float* B, int ldb,
                       float* C, int ldc, int M, int N, int K,
                       const float* bias,
                       int batches = 1, int dv = 1,
                       long long aHi = 0, long long aLo = 0,
                       long long bHi = 0, long long bLo = 0,
                       long long cHi = 0, long long cLo = 0)
{
    dim3 grid((N + 127) / 128, M / 128, batches);
    tgemm_big<<<grid, 256, BIG_SMEM_BYTES>>>(A, lda, B, ldb, C, ldc, M, N, K, bias, dv,
                                             aHi, aLo, bHi, bLo, cHi, cLo);
}

static void gemm_mlp_l(const float* A, int lda, const float* B, int ldb,
                       float* C, int ldc, int M, int N, int K,
                       const float* bias, int act, bool acc)
{
    dim3 grid((N + 63) / 64, M / 128, 1);
    if (acc) tgemm_mlp<true ><<<grid, 256>>>(A, lda, B, ldb, C, ldc, M, N, K, bias, act);
    else     tgemm_mlp<false><<<grid, 256>>>(A, lda, B, ldb, C, ldc, M, N, K, bias, act);
}

extern "C" void kernel_launch(void* const* d_in, const int* in_sizes, int n_in,
                              void* d_out, int out_size)
{
    const float* h_in  = (const float*)d_in[1];
    const float* e     = (const float*)d_in[2];
    const float* Amat  = (const float*)d_in[3];
    const float* Wih   = (const float*)d_in[4];
    const float* Whh   = (const float*)d_in[5];
    const float* bih   = (const float*)d_in[6];
    const float* bhh   = (const float*)d_in[7];

    cudaFuncSetAttribute(tgemm_big, cudaFuncAttributeMaxDynamicSharedMemorySize, BIG_SMEM_BYTES);

    const float *r1W[4], *r1b[4], *r2W[4], *r2b[4];
    if (in_sizes[10] == 65536) {
        for (int i = 0; i < 4; i++) {
            r1W[i] = (const float*)d_in[8 + 4 * i];
            r1b[i] = (const float*)d_in[9 + 4 * i];
            r2W[i] = (const float*)d_in[10 + 4 * i];
            r2b[i] = (const float*)d_in[11 + 4 * i];
        }
    } else {
        for (int i = 0; i < 4; i++) {
            r1W[i] = (const float*)d_in[8 + 2 * i];
            r1b[i] = (const float*)d_in[9 + 2 * i];
            r2W[i] = (const float*)d_in[16 + 2 * i];
            r2b[i] = (const float*)d_in[17 + 2 * i];
        }
    }
    float* out = (float*)d_out;

    float *h_, *hproj, *m_, *gi, *gh, *mask, *t0, *t1, *gate, *val, *AT;
    cudaGetSymbolAddress((void**)&h_,    g_h);
    cudaGetSymbolAddress((void**)&hproj, g_hproj);
    cudaGetSymbolAddress((void**)&m_,    g_m);
    cudaGetSymbolAddress((void**)&gi,    g_gi);
    cudaGetSymbolAddress((void**)&gh,    g_gh);
    cudaGetSymbolAddress((void**)&mask,  g_mask);
    cudaGetSymbolAddress((void**)&t0,    g_t0);
    cudaGetSymbolAddress((void**)&t1,    g_t1);
    cudaGetSymbolAddress((void**)&gate,  g_gate);
    cudaGetSymbolAddress((void**)&val,   g_val);
    cudaGetSymbolAddress((void**)&AT,    g_AT);

    init_kernel<<<ROWS, 128>>>(h_in, h_, mask);
    {
        dim3 tg(HH / 32, MSGD / 32, LL);
        transposeA_kernel<<<tg, dim3(32, 8)>>>(Amat, AT);
    }

    for (int step = 0; step < 4; step++) {
        // hproj[b,l] = h[b] @ A[l] ; A[l] as TRANSB via AT[l] ([MSG][H] row-major)
        gemm_big_l(h_, HH, AT, HH, hproj, MSGD,
                   NN, MSGD, HH, nullptr,
                   /*batches=*/BQ * LL, /*dv=*/LL,
                   (long long)NN * HH, 0,
                   0, (long long)HH * MSGD,
                   (long long)LL * NN * MSGD, (long long)NN * MSGD);

        agg_kernel<<<ROWS, 128>>>(e, hproj, m_);

        gemm_big_l(m_, MSGD, Wih, MSGD, gi, 3 * HH, ROWS, 3 * HH, MSGD, bih);
        gemm_big_l(h_, HH,   Whh, HH,   gh, 3 * HH, ROWS, 3 * HH, HH,   bhh);

        gru_kernel<<<ROWS, 128>>>(h_, gi, gh, mask);
    }

    // gate chain: relu(concat(h,h0) @ W0^T + b0) as two GEMMs (h0 tail = h_in pad)
    gemm_mlp_l(h_,   HH,  r1W[0],      2 * HH, t0, 128, ROWS, 128, HH,  nullptr, 0, false);
    gemm_mlp_l(h_in, FIN, r1W[0] + HH, 2 * HH, t0, 128, ROWS, 128, FIN, r1b[0],  1, true);
    gemm_mlp_l(t0, 128, r1W[1], 128, t1, 256, ROWS, 256, 128, r1b[1], 1, false);
    gemm_mlp_l(t1, 256, r1W[2], 256, t0, 128, ROWS, 128, 256, r1b[2], 1, false);
    gemm_mlp_l(t0, 128, r1W[3], 128, gate, TGT, ROWS, TGT, 128, r1b[3], 2, false);

    // val chain
    gemm_mlp_l(h_, HH,  r2W[0], HH,  t0, 128, ROWS, 128, HH,  r2b[0], 1, false);
    gemm_mlp_l(t0, 128, r2W[1], 128, t1, 256, ROWS, 256, 128, r2b[1], 1, false);
    gemm_mlp_l(t1, 256, r2W[2], 256, t0, 128, ROWS, 128, 256, r2b[2], 1, false);
    gemm_mlp_l(t0, 128, r2W[3], 128, val, TGT, ROWS, TGT, 128, r2b[3], 0, false);

    reduce_kernel<<<BQ, 128>>>(gate, val, mask, out);
}

// round 14
// speedup vs baseline: 1.5594x; 1.0961x over previous
#include <cuda_runtime.h>
#include <cuda_bf16.h>
#include <cstdint>

// Problem constants
#define BQ   64
#define NN   128
#define FIN  128
#define HH   512
#define MSGD 512
#define LL   4
#define ROWS (BQ*NN)      // 8192
#define TGT  12

typedef __nv_bfloat16 bf16;

// ---------------- scratch (device globals) ----------------
__device__ float g_h    [ROWS*HH];
__device__ float g_hproj[BQ*LL*NN*MSGD];
__device__ float g_gi   [ROWS*3*HH];
__device__ float g_gh   [ROWS*3*HH];
__device__ float g_mask [ROWS];
__device__ float g_t0f  [ROWS*128];        // f32 partial for gate L0 accumulation
__device__ float g_gate [ROWS*TGT];
__device__ float g_val  [ROWS*TGT];
// bf16 hi/lo planes
__device__ bf16 g_hh[ROWS*HH],    g_hl[ROWS*HH];
__device__ bf16 g_mh[ROWS*MSGD],  g_ml[ROWS*MSGD];
__device__ bf16 g_hinh[ROWS*FIN], g_hinl[ROWS*FIN];
__device__ bf16 g_t0h[ROWS*256],  g_t0l[ROWS*256];
__device__ bf16 g_t1h[ROWS*256],  g_t1l[ROWS*256];
__device__ bf16 g_ATh[LL*HH*MSGD],  g_ATl[LL*HH*MSGD];
__device__ bf16 g_Wihh[3*HH*MSGD],  g_Wihl[3*HH*MSGD];
__device__ bf16 g_Whhh[3*HH*HH],    g_Whhl[3*HH*HH];
__device__ bf16 g_rwh[512*1024],    g_rwl[512*1024];   // pooled readout weights

// ---------------- helpers ----------------
__device__ __forceinline__ void bsplit1(float x, uint16_t& h, uint16_t& l) {
    bf16 b = __float2bfloat16_rn(x);
    h = __bfloat16_as_ushort(b);
    l = __bfloat16_as_ushort(__float2bfloat16_rn(x - __bfloat162float(b)));
}
__device__ __forceinline__ void mma_bf16(float* d, const uint32_t* a, const uint32_t* b) {
    asm volatile(
        "mma.sync.aligned.m16n8k16.row.col.f32.bf16.bf16.f32 "
        "{%0,%1,%2,%3}, {%4,%5,%6,%7}, {%8,%9}, {%0,%1,%2,%3};\n"
        : "+f"(d[0]), "+f"(d[1]), "+f"(d[2]), "+f"(d[3])
        : "r"(a[0]), "r"(a[1]), "r"(a[2]), "r"(a[3]), "r"(b[0]), "r"(b[1]));
}
__device__ __forceinline__ void ldsm_x4(uint32_t& r0, uint32_t& r1, uint32_t& r2, uint32_t& r3,
                                        uint32_t addr) {
    asm volatile("ldmatrix.sync.aligned.m8n8.x4.shared.b16 {%0,%1,%2,%3}, [%4];"
                 : "=r"(r0), "=r"(r1), "=r"(r2), "=r"(r3) : "r"(addr));
}
__device__ __forceinline__ void cp16(uint32_t dst, const void* src) {
    asm volatile("cp.async.cg.shared.global [%0], [%1], 16;" :: "r"(dst), "l"(src));
}
__device__ __forceinline__ void cp16z(uint32_t dst, const void* src, int srcsize) {
    asm volatile("cp.async.cg.shared.global [%0], [%1], 16, %2;" :: "r"(dst), "l"(src), "r"(srcsize));
}
#define CP_COMMIT() asm volatile("cp.async.commit_group;")
#define CP_WAIT1()  asm volatile("cp.async.wait_group 1;")

#define ROWB 48            // smem row: 16 bf16 (32B) + 16B pad
#define PIPE 3

// ================= BIG kernel: 128x128, BK=16, cp.async 3-stage, 2 CTAs/SM ==========
#define PLB   (128 * ROWB)          // 6144 B per plane
#define STGB  (4 * PLB)             // 24576 B per stage
#define BIG_SMEM_BYTES (PIPE * STGB)  // 73728 B

__global__ void __launch_bounds__(256, 2)
tgemm_big(const bf16* __restrict__ Ah_, const bf16* __restrict__ Al_, int lda,
          const bf16* __restrict__ Bh_, const bf16* __restrict__ Bl_, int ldb,
          float* __restrict__ C, int ldc,
          int K, const float* __restrict__ bias,
          int dv,
          long long aHi, long long aLo,
          long long bHi, long long bLo,
          long long cHi, long long cLo)
{
    extern __shared__ char smc[];

    int z = blockIdx.z;
    int zh = z / dv, zl = z % dv;
    Ah_ += zh*aHi + zl*aLo;  Al_ += zh*aHi + zl*aLo;
    Bh_ += zh*bHi + zl*bLo;  Bl_ += zh*bHi + zl*bLo;
    C   += zh*cHi + zl*cLo;

    int tid  = threadIdx.x;
    int lane = tid & 31;
    int wid  = tid >> 5;
    int gid  = lane >> 2;
    int tig  = lane & 3;
    int quad = lane >> 3;
    int rowin= lane & 7;
    int wm   = (wid & 3) * 32;
    int wn   = (wid >> 2) * 64;
    int m0   = blockIdx.y * 128;
    int n0   = blockIdx.x * 128;

    uint32_t sbase = (uint32_t)__cvta_generic_to_shared(smc);

    int aoff = ((quad & 1) * 8 + rowin) * ROWB + ((quad >> 1) * 16);
    int boff = ((quad >> 1) * 8 + rowin) * ROWB + ((quad & 1) * 16);

    // cp.async mapping: 256 threads cover 128 rows x 2 16B-chunks per plane
    int cr = tid >> 1;                 // row 0..127
    int cc = (tid & 1) * 16;           // byte chunk 0 or 16
    const char* baseAh = (const char*)(Ah_ + (size_t)(m0 + cr) * lda) + cc;
    const char* baseAl = (const char*)(Al_ + (size_t)(m0 + cr) * lda) + cc;
    const char* baseBh = (const char*)(Bh_ + (size_t)(n0 + cr) * ldb) + cc;
    const char* baseBl = (const char*)(Bl_ + (size_t)(n0 + cr) * ldb) + cc;
    uint32_t dstA = sbase + cr * ROWB + cc;

    auto cpstage = [&](int s, int k0) {
        uint32_t d = dstA + s * STGB;
        size_t go = (size_t)k0 * 2;
        cp16(d,           baseAh + go);
        cp16(d + PLB,     baseAl + go);
        cp16(d + 2*PLB,   baseBh + go);
        cp16(d + 3*PLB,   baseBl + go);
    };

    float acc[2][8][4];
#pragma unroll
    for (int mt = 0; mt < 2; mt++)
#pragma unroll
        for (int nt = 0; nt < 8; nt++)
#pragma unroll
            for (int q = 0; q < 4; q++) acc[mt][nt][q] = 0.f;

    // prologue: stages 0..PIPE-2
#pragma unroll
    for (int s = 0; s < PIPE - 1; s++) {
        cpstage(s, s * 16);
        CP_COMMIT();
    }
    CP_WAIT1();
    __syncthreads();

    int rd = 0, wr = PIPE - 1;
    for (int k0 = 0; k0 < K; k0 += 16) {
        int pk = k0 + (PIPE - 1) * 16;
        if (pk < K) cpstage(wr, pk);
        CP_COMMIT();

        uint32_t bb  = sbase + rd * STGB;
        uint32_t ahp = bb + wm * ROWB + aoff;
        uint32_t alp = ahp + PLB;
        uint32_t bhp = bb + 2*PLB + wn * ROWB + boff;
        uint32_t blp = bhp + PLB;

        uint32_t afh[2][4], afl[2][4], bfh[8][2], bfl[8][2];
        ldsm_x4(afh[0][0], afh[0][1], afh[0][2], afh[0][3], ahp);
        ldsm_x4(afh[1][0], afh[1][1], afh[1][2], afh[1][3], ahp + 16 * ROWB);
        ldsm_x4(afl[0][0], afl[0][1], afl[0][2], afl[0][3], alp);
        ldsm_x4(afl[1][0], afl[1][1], afl[1][2], afl[1][3], alp + 16 * ROWB);
#pragma unroll
        for (int p = 0; p < 4; p++) {
            ldsm_x4(bfh[2*p][0], bfh[2*p][1], bfh[2*p+1][0], bfh[2*p+1][1], bhp + p * 16 * ROWB);
            ldsm_x4(bfl[2*p][0], bfl[2*p][1], bfl[2*p+1][0], bfl[2*p+1][1], blp + p * 16 * ROWB);
        }
#pragma unroll
        for (int mt = 0; mt < 2; mt++)
#pragma unroll
            for (int nt = 0; nt < 8; nt++) {
                mma_bf16(acc[mt][nt], afl[mt], bfh[nt]);
                mma_bf16(acc[mt][nt], afh[mt], bfl[nt]);
                mma_bf16(acc[mt][nt], afh[mt], bfh[nt]);
            }
        CP_WAIT1();
        __syncthreads();
        rd = (rd + 1) % PIPE;
        wr = (wr + 1) % PIPE;
    }

#pragma unroll
    for (int mt = 0; mt < 2; mt++) {
#pragma unroll
        for (int nt = 0; nt < 8; nt++) {
            int row = m0 + wm + mt * 16 + gid;
            int col = n0 + wn + nt * 8 + tig * 2;
#pragma unroll
            for (int half = 0; half < 2; half++) {
                int r = row + half * 8;
                float v0 = acc[mt][nt][half * 2 + 0];
                float v1 = acc[mt][nt][half * 2 + 1];
                size_t idx = (size_t)r * ldc + col;
                if (bias) {
                    v0 += __ldg(bias + col);
                    v1 += __ldg(bias + col + 1);
                }
                *(float2*)(C + idx) = make_float2(v0, v1);
            }
        }
    }
}

// ================= MLP kernel: 128x64, cp.async 3-stage, plane in / plane-or-f32 out =====
#define PLA_M  (128 * ROWB)         // 6144
#define PLB_M  (64 * ROWB)          // 3072
#define STG_M  (2 * PLA_M + 2 * PLB_M)   // 18432
#define MLP_SMEM (PIPE * STG_M)     // 55296 -> dynamic

template<bool ACC>
__global__ void __launch_bounds__(256, 2)
tgemm_mlp(const bf16* __restrict__ Ah_, const bf16* __restrict__ Al_, int lda,
          const bf16* __restrict__ Bh_, const bf16* __restrict__ Bl_, int ldb,
          int N, int K,
          const float* __restrict__ bias, int act,
          const float* __restrict__ Cacc,
          float* __restrict__ Cf, bf16* __restrict__ Ch, bf16* __restrict__ Cl,
          int ldc, int outmode)
{
    extern __shared__ char smc[];

    int tid  = threadIdx.x;
    int lane = tid & 31;
    int wid  = tid >> 5;
    int gid  = lane >> 2;
    int tig  = lane & 3;
    int quad = lane >> 3;
    int rowin= lane & 7;
    int wm   = (wid & 3) * 32;
    int wn   = (wid >> 2) * 32;
    int m0   = blockIdx.y * 128;
    int n0   = blockIdx.x * 64;

    uint32_t sbase = (uint32_t)__cvta_generic_to_shared(smc);
    int aoff = ((quad & 1) * 8 + rowin) * ROWB + ((quad >> 1) * 16);
    int boff = ((quad >> 1) * 8 + rowin) * ROWB + ((quad & 1) * 16);

    int cr = tid >> 1;
    int cc = (tid & 1) * 16;
    const char* baseAh = (const char*)(Ah_ + (size_t)(m0 + cr) * lda) + cc;
    const char* baseAl = (const char*)(Al_ + (size_t)(m0 + cr) * lda) + cc;
    int brow = cr & 63;
    int bok  = (cr < 64) && (n0 + brow < N);
    int bsz  = bok ? 16 : 0;
    int brc  = bok ? (n0 + brow) : 0;
    const char* baseBh = (const char*)(Bh_ + (size_t)brc * ldb) + cc;
    const char* baseBl = (const char*)(Bl_ + (size_t)brc * ldb) + cc;
    uint32_t dstA = sbase + cr * ROWB + cc;
    uint32_t dstB = sbase + 2*PLA_M + brow * ROWB + cc;

    auto cpstage = [&](int s, int k0) {
        size_t go = (size_t)k0 * 2;
        cp16(dstA + s * STG_M,         baseAh + go);
        cp16(dstA + s * STG_M + PLA_M, baseAl + go);
        if (cr < 64) {
            cp16z(dstB + s * STG_M,         baseBh + go, bsz);
            cp16z(dstB + s * STG_M + PLB_M, baseBl + go, bsz);
        }
    };

    float acc[2][4][4];
#pragma unroll
    for (int mt = 0; mt < 2; mt++)
#pragma unroll
        for (int nt = 0; nt < 4; nt++)
#pragma unroll
            for (int q = 0; q < 4; q++) acc[mt][nt][q] = 0.f;

#pragma unroll
    for (int s = 0; s < PIPE - 1; s++) {
        if (s * 16 < K) cpstage(s, s * 16);
        CP_COMMIT();
    }
    CP_WAIT1();
    __syncthreads();

    int rd = 0, wr = PIPE - 1;
    for (int k0 = 0; k0 < K; k0 += 16) {
        int pk = k0 + (PIPE - 1) * 16;
        if (pk < K) cpstage(wr, pk);
        CP_COMMIT();

        uint32_t bb  = sbase + rd * STG_M;
        uint32_t ahp = bb + wm * ROWB + aoff;
        uint32_t alp = ahp + PLA_M;
        uint32_t bhp = bb + 2*PLA_M + wn * ROWB + boff;
        uint32_t blp = bhp + PLB_M;

        uint32_t afh[2][4], afl[2][4], bfh[4][2], bfl[4][2];
        ldsm_x4(afh[0][0], afh[0][1], afh[0][2], afh[0][3], ahp);
        ldsm_x4(afh[1][0], afh[1][1], afh[1][2], afh[1][3], ahp + 16 * ROWB);
        ldsm_x4(afl[0][0], afl[0][1], afl[0][2], afl[0][3], alp);
        ldsm_x4(afl[1][0], afl[1][1], afl[1][2], afl[1][3], alp + 16 * ROWB);
#pragma unroll
        for (int p = 0; p < 2; p++) {
            ldsm_x4(bfh[2*p][0], bfh[2*p][1], bfh[2*p+1][0], bfh[2*p+1][1], bhp + p * 16 * ROWB);
            ldsm_x4(bfl[2*p][0], bfl[2*p][1], bfl[2*p+1][0], bfl[2*p+1][1], blp + p * 16 * ROWB);
        }
#pragma unroll
        for (int mt = 0; mt < 2; mt++)
#pragma unroll
            for (int nt = 0; nt < 4; nt++) {
                mma_bf16(acc[mt][nt], afl[mt], bfh[nt]);
                mma_bf16(acc[mt][nt], afh[mt], bfl[nt]);
                mma_bf16(acc[mt][nt], afh[mt], bfh[nt]);
            }
        CP_WAIT1();
        __syncthreads();
        rd = (rd + 1) % PIPE;
        wr = (wr + 1) % PIPE;
    }

#pragma unroll
    for (int mt = 0; mt < 2; mt++) {
#pragma unroll
        for (int nt = 0; nt < 4; nt++) {
            int row = m0 + wm + mt * 16 + gid;
            int col = n0 + wn + nt * 8 + tig * 2;
            if (col < N) {
#pragma unroll
                for (int half = 0; half < 2; half++) {
                    int r = row + half * 8;
                    float v0 = acc[mt][nt][half * 2 + 0];
                    float v1 = acc[mt][nt][half * 2 + 1];
                    size_t idx = (size_t)r * ldc + col;
                    if (ACC) {
                        float2 old = *(const float2*)(Cacc + idx);
                        v0 += old.x; v1 += old.y;
                    }
                    if (bias) {
                        v0 += __ldg(bias + col);
                        v1 += __ldg(bias + col + 1);
                    }
                    if (act == 1) { v0 = fmaxf(v0, 0.f); v1 = fmaxf(v1, 0.f); }
                    else if (act == 2) {
                        v0 = 1.f / (1.f + __expf(-v0));
                        v1 = 1.f / (1.f + __expf(-v1));
                    }
                    if (outmode == 0) {
                        *(float2*)(Cf + idx) = make_float2(v0, v1);
                    } else {
                        uint16_t h0, l0, h1, l1;
                        bsplit1(v0, h0, l0);
                        bsplit1(v1, h1, l1);
                        *(uint32_t*)(Ch + idx) = (uint32_t)h0 | ((uint32_t)h1 << 16);
                        *(uint32_t*)(Cl + idx) = (uint32_t)l0 | ((uint32_t)l1 << 16);
                    }
                }
            }
        }
    }
}

// ---------------- conversion / transpose ----------------
__global__ void convert_kernel(const float* __restrict__ src,
                               bf16* __restrict__ dh, bf16* __restrict__ dl, int n)
{
    int i = blockIdx.x * 256 + threadIdx.x;
    if (i < n) {
        float x = src[i];
        bf16 h = __float2bfloat16_rn(x);
        dh[i] = h;
        dl[i] = __float2bfloat16_rn(x - __bfloat162float(h));
    }
}

// Amat [l][k][m] -> AT planes [l][m][k]
__global__ void transposeA_kernel(const float* __restrict__ Amat,
                                  bf16* __restrict__ ATh, bf16* __restrict__ ATl)
{
    __shared__ float tile[32][33];
    int l = blockIdx.z;
    int kb = blockIdx.x * 32;
    int mb = blockIdx.y * 32;
    const float* src = Amat + (size_t)l * HH * MSGD;
    int tx = threadIdx.x, ty = threadIdx.y;
#pragma unroll
    for (int i = 0; i < 4; i++)
        tile[ty + i * 8][tx] = src[(size_t)(kb + ty + i * 8) * MSGD + mb + tx];
    __syncthreads();
#pragma unroll
    for (int i = 0; i < 4; i++) {
        int m = mb + ty + i * 8;
        float x = tile[tx][ty + i * 8];
        bf16 h = __float2bfloat16_rn(x);
        size_t o = (size_t)l * HH * MSGD + (size_t)m * HH + kb + tx;
        ATh[o] = h;
        ATl[o] = __float2bfloat16_rn(x - __bfloat162float(h));
    }
}

// ---------------- elementwise kernels ----------------
__global__ void init_kernel(const float* __restrict__ h_in,
                            float* __restrict__ h, float* __restrict__ mask,
                            bf16* __restrict__ hh, bf16* __restrict__ hl,
                            bf16* __restrict__ hinh, bf16* __restrict__ hinl)
{
    int row = blockIdx.x;
    int t = threadIdx.x;   // 128
    float v = h_in[(size_t)row * FIN + t];
    float s = fabsf(v);
#pragma unroll
    for (int o = 16; o; o >>= 1) s += __shfl_xor_sync(0xffffffffu, s, o);
    __shared__ float ws[4];
    if ((t & 31) == 0) ws[t >> 5] = s;
    __syncthreads();
    if (t == 0) {
        float tot = ws[0] + ws[1] + ws[2] + ws[3];
        mask[row] = (tot > 0.f) ? 1.f : 0.f;
    }
    size_t rb = (size_t)row * HH;
    h[rb + t] = v;
    h[rb + t + 128] = 0.f; h[rb + t + 256] = 0.f; h[rb + t + 384] = 0.f;
    uint16_t hi, lo;
    bsplit1(v, hi, lo);
    hh[rb + t] = __ushort_as_bfloat16(hi);
    hl[rb + t] = __ushort_as_bfloat16(lo);
    bf16 z = __float2bfloat16_rn(0.f);
    hh[rb + t + 128] = z; hh[rb + t + 256] = z; hh[rb + t + 384] = z;
    hl[rb + t + 128] = z; hl[rb + t + 256] = z; hl[rb + t + 384] = z;
    hinh[(size_t)row * FIN + t] = __ushort_as_bfloat16(hi);
    hinl[(size_t)row * FIN + t] = __ushort_as_bfloat16(lo);
}

__global__ void agg_kernel(const float* __restrict__ e,
                           const float* __restrict__ hproj,
                           bf16* __restrict__ mh, bf16* __restrict__ ml)
{
    int row = blockIdx.x;          // b*128 + v
    int b = row >> 7;
    int t = threadIdx.x;           // 128
    __shared__ int cnt;
    __shared__ int widx[NN];
    __shared__ int wlab[NN];
    if (t == 0) cnt = 0;
    __syncthreads();
    float ev = e[(size_t)row * NN + t];
    int lab = (int)(ev + 0.5f);
    if (lab >= 1) {
        int p = atomicAdd(&cnt, 1);
        widx[p] = t;
        wlab[p] = lab - 1;
    }
    __syncthreads();
    float a0 = 0.f, a1 = 0.f, a2 = 0.f, a3 = 0.f;
    int n = cnt;
    const float* hb = hproj + (size_t)b * LL * NN * MSGD;
    for (int i = 0; i < n; i++) {
        const float* src = hb + ((size_t)wlab[i] * NN + widx[i]) * MSGD;
        a0 += __ldg(src + t);
        a1 += __ldg(src + t + 128);
        a2 += __ldg(src + t + 256);
        a3 += __ldg(src + t + 384);
    }
    size_t o = (size_t)row * MSGD;
    float vals[4] = {a0, a1, a2, a3};
#pragma unroll
    for (int j = 0; j < 4; j++) {
        uint16_t hi, lo;
        bsplit1(vals[j], hi, lo);
        mh[o + t + j * 128] = __ushort_as_bfloat16(hi);
        ml[o + t + j * 128] = __ushort_as_bfloat16(lo);
    }
}

__global__ void gru_kernel(float* __restrict__ h,
                           const float* __restrict__ gi,
                           const float* __restrict__ gh,
                           const float* __restrict__ mask,
                           bf16* __restrict__ hh, bf16* __restrict__ hl)
{
    int row = blockIdx.x;
    int t = threadIdx.x;   // 128
    float mk = mask[row];
    const float* gir = gi + (size_t)row * 3 * HH;
    const float* ghr = gh + (size_t)row * 3 * HH;
    float* hr = h + (size_t)row * HH;
    size_t rb = (size_t)row * HH;
#pragma unroll
    for (int j = 0; j < 4; j++) {
        int idx = t + j * 128;
        float ir = gir[idx], iz = gir[idx + HH], in_ = gir[idx + 2 * HH];
        float hrv = ghr[idx], hz = ghr[idx + HH], hn = ghr[idx + 2 * HH];
        float r  = 1.f / (1.f + __expf(-(ir + hrv)));
        float z  = 1.f / (1.f + __expf(-(iz + hz)));
        float nn = tanhf(in_ + r * hn);
        float ho = hr[idx];
        float v = ((1.f - z) * nn + z * ho) * mk;
        hr[idx] = v;
        uint16_t hi, lo;
        bsplit1(v, hi, lo);
        hh[rb + idx] = __ushort_as_bfloat16(hi);
        hl[rb + idx] = __ushort_as_bfloat16(lo);
    }
}

__global__ void reduce_kernel(const float* __restrict__ gate,
                              const float* __restrict__ val,
                              const float* __restrict__ mask,
                              float* __restrict__ out)
{
    __shared__ float sm[TGT][NN];
    int b = blockIdx.x;
    int t = threadIdx.x;   // 128
    int row = b * NN + t;
    float mk = mask[row];
#pragma unroll
    for (int j = 0; j < TGT; j++)
        sm[j][t] = gate[(size_t)row * TGT + j] * val[(size_t)row * TGT + j] * mk;
    __syncthreads();
    for (int s = 64; s > 0; s >>= 1) {
        if (t < s) {
#pragma unroll
            for (int j = 0; j < TGT; j++) sm[j][t] += sm[j][t + s];
        }
        __syncthreads();
    }
    if (t < TGT) out[b * TGT + t] = sm[t][0];
}

// ---------------- host side ----------------
static void gemm_big_l(const bf16* Ah, const bf16* Al, int lda,
                       const bf16* Bh, const bf16* Bl, int ldb,
                       float* C, int ldc, int M, int N, int K,
                       const float* bias,
                       int batches = 1, int dv = 1,
                       long long aHi = 0, long long aLo = 0,
                       long long bHi = 0, long long bLo = 0,
                       long long cHi = 0, long long cLo = 0)
{
    dim3 grid(N / 128, M / 128, batches);
    tgemm_big<<<grid, 256, BIG_SMEM_BYTES>>>(Ah, Al, lda, Bh, Bl, ldb, C, ldc, K, bias,
                                             dv, aHi, aLo, bHi, bLo, cHi, cLo);
}

static void gemm_mlp_l(const bf16* Ah, const bf16* Al, int lda,
                       const bf16* Bh, const bf16* Bl, int ldb,
                       int M, int N, int K, const float* bias, int act, bool acc,
                       const float* Cacc, float* Cf, bf16* Ch, bf16* Cl, int ldc, int outmode)
{
    dim3 grid((N + 63) / 64, M / 128, 1);
    if (acc) tgemm_mlp<true ><<<grid, 256, MLP_SMEM>>>(Ah, Al, lda, Bh, Bl, ldb, N, K, bias, act, Cacc, Cf, Ch, Cl, ldc, outmode);
    else     tgemm_mlp<false><<<grid, 256, MLP_SMEM>>>(Ah, Al, lda, Bh, Bl, ldb, N, K, bias, act, Cacc, Cf, Ch, Cl, ldc, outmode);
}

extern "C" void kernel_launch(void* const* d_in, const int* in_sizes, int n_in,
                              void* d_out, int out_size)
{
    const float* h_in  = (const float*)d_in[1];
    const float* e     = (const float*)d_in[2];
    const float* Amat  = (const float*)d_in[3];
    const float* Wih   = (const float*)d_in[4];
    const float* Whh   = (const float*)d_in[5];
    const float* bih   = (const float*)d_in[6];
    const float* bhh   = (const float*)d_in[7];

    cudaFuncSetAttribute(tgemm_big, cudaFuncAttributeMaxDynamicSharedMemorySize, BIG_SMEM_BYTES);
    cudaFuncSetAttribute(tgemm_mlp<true >, cudaFuncAttributeMaxDynamicSharedMemorySize, MLP_SMEM);
    cudaFuncSetAttribute(tgemm_mlp<false>, cudaFuncAttributeMaxDynamicSharedMemorySize, MLP_SMEM);

    const float *r1W[4], *r1b[4], *r2W[4], *r2b[4];
    if (in_sizes[10] == 65536) {
        for (int i = 0; i < 4; i++) {
            r1W[i] = (const float*)d_in[8 + 4 * i];
            r1b[i] = (const float*)d_in[9 + 4 * i];
            r2W[i] = (const float*)d_in[10 + 4 * i];
            r2b[i] = (const float*)d_in[11 + 4 * i];
        }
    } else {
        for (int i = 0; i < 4; i++) {
            r1W[i] = (const float*)d_in[8 + 2 * i];
            r1b[i] = (const float*)d_in[9 + 2 * i];
            r2W[i] = (const float*)d_in[16 + 2 * i];
            r2b[i] = (const float*)d_in[17 + 2 * i];
        }
    }
    float* out = (float*)d_out;

    float *h_, *hproj, *gi, *gh, *mask, *t0f, *gate, *val;
    cudaGetSymbolAddress((void**)&h_,    g_h);
    cudaGetSymbolAddress((void**)&hproj, g_hproj);
    cudaGetSymbolAddress((void**)&gi,    g_gi);
    cudaGetSymbolAddress((void**)&gh,    g_gh);
    cudaGetSymbolAddress((void**)&mask,  g_mask);
    cudaGetSymbolAddress((void**)&t0f,   g_t0f);
    cudaGetSymbolAddress((void**)&gate,  g_gate);
    cudaGetSymbolAddress((void**)&val,   g_val);

    bf16 *hh, *hl, *mh, *ml, *hinh, *hinl, *t0h, *t0l, *t1h, *t1l;
    bf16 *ATh, *ATl, *Wihh, *Wihl, *Whhh, *Whhl, *rwh, *rwl;
    cudaGetSymbolAddress((void**)&hh,   g_hh);   cudaGetSymbolAddress((void**)&hl,   g_hl);
    cudaGetSymbolAddress((void**)&mh,   g_mh);   cudaGetSymbolAddress((void**)&ml,   g_ml);
    cudaGetSymbolAddress((void**)&hinh, g_hinh); cudaGetSymbolAddress((void**)&hinl, g_hinl);
    cudaGetSymbolAddress((void**)&t0h,  g_t0h);  cudaGetSymbolAddress((void**)&t0l,  g_t0l);
    cudaGetSymbolAddress((void**)&t1h,  g_t1h);  cudaGetSymbolAddress((void**)&t1l,  g_t1l);
    cudaGetSymbolAddress((void**)&ATh,  g_ATh);  cudaGetSymbolAddress((void**)&ATl,  g_ATl);
    cudaGetSymbolAddress((void**)&Wihh, g_Wihh); cudaGetSymbolAddress((void**)&Wihl, g_Wihl);
    cudaGetSymbolAddress((void**)&Whhh, g_Whhh); cudaGetSymbolAddress((void**)&Whhl, g_Whhl);
    cudaGetSymbolAddress((void**)&rwh,  g_rwh);  cudaGetSymbolAddress((void**)&rwl,  g_rwl);

    // readout weight pool offsets
    const int O_R1W0 = 0;                       // 128*1024
    const int O_R1W1 = O_R1W0 + 128 * 1024;     // 256*128
    const int O_R1W2 = O_R1W1 + 256 * 128;      // 128*256
    const int O_R1W3 = O_R1W2 + 128 * 256;      // 12*128
    const int O_R2W0 = O_R1W3 + 12 * 128;       // 128*512
    const int O_R2W1 = O_R2W0 + 128 * 512;      // 256*128
    const int O_R2W2 = O_R2W1 + 256 * 128;      // 128*256
    const int O_R2W3 = O_R2W2 + 128 * 256;      // 12*128

    // one-time conversions (idempotent each launch)
    auto conv = [&](const float* s, bf16* dh, bf16* dl, int n) {
        convert_kernel<<<(n + 255) / 256, 256>>>(s, dh, dl, n);
    };
    conv(Wih, Wihh, Wihl, 3 * HH * MSGD);
    conv(Whh, Whhh, Whhl, 3 * HH * HH);
    conv(r1W[0], rwh + O_R1W0, rwl + O_R1W0, 128 * 1024);
    conv(r1W[1], rwh + O_R1W1, rwl + O_R1W1, 256 * 128);
    conv(r1W[2], rwh + O_R1W2, rwl + O_R1W2, 128 * 256);
    conv(r1W[3], rwh + O_R1W3, rwl + O_R1W3, 12 * 128);
    conv(r2W[0], rwh + O_R2W0, rwl + O_R2W0, 128 * 512);
    conv(r2W[1], rwh + O_R2W1, rwl + O_R2W1, 256 * 128);
    conv(r2W[2], rwh + O_R2W2, rwl + O_R2W2, 128 * 256);
    conv(r2W[3], rwh + O_R2W3, rwl + O_R2W3, 12 * 128);
    {
        dim3 tg(HH / 32, MSGD / 32, LL);
        transposeA_kernel<<<tg, dim3(32, 8)>>>(Amat, ATh, ATl);
    }

    init_kernel<<<ROWS, 128>>>(h_in, h_, mask, hh, hl, hinh, hinl);

    for (int step = 0; step < 4; step++) {
        // hproj[b,l] = h[b] @ AT[l]^T  (batched, TRANSB planes)
        gemm_big_l(hh, hl, HH, ATh, ATl, HH, hproj, MSGD,
                   NN, MSGD, HH, nullptr,
                   BQ * LL, LL,
                   (long long)NN * HH, 0,
                   0, (long long)HH * MSGD,
                   (long long)LL * NN * MSGD, (long long)NN * MSGD);

        agg_kernel<<<ROWS, 128>>>(e, hproj, mh, ml);

        gemm_big_l(mh, ml, MSGD, Wihh, Wihl, MSGD, gi, 3 * HH, ROWS, 3 * HH, MSGD, bih);
        gemm_big_l(hh, hl, HH,   Whhh, Whhl, HH,   gh, 3 * HH, ROWS, 3 * HH, HH,   bhh);

        gru_kernel<<<ROWS, 128>>>(h_, gi, gh, mask, hh, hl);
    }

    // gate chain
    gemm_mlp_l(hh, hl, HH, rwh + O_R1W0, rwl + O_R1W0, 1024,
               ROWS, 128, HH, nullptr, 0, false, nullptr, t0f, nullptr, nullptr, 128, 0);
    gemm_mlp_l(hinh, hinl, FIN, rwh + O_R1W0 + 512, rwl + O_R1W0 + 512, 1024,
               ROWS, 128, FIN, r1b[0], 1, true, t0f, nullptr, t0h, t0l, 128, 1);
    gemm_mlp_l(t0h, t0l, 128, rwh + O_R1W1, rwl + O_R1W1, 128,
               ROWS, 256, 128, r1b[1], 1, false, nullptr, nullptr, t1h, t1l, 256, 1);
    gemm_mlp_l(t1h, t1l, 256, rwh + O_R1W2, rwl + O_R1W2, 256,
               ROWS, 128, 256, r1b[2], 1, false, nullptr, nullptr, t0h, t0l, 128, 1);
    gemm_mlp_l(t0h, t0l, 128, rwh + O_R1W3, rwl + O_R1W3, 128,
               ROWS, TGT, 128, r1b[3], 2, false, nullptr, gate, nullptr, nullptr, TGT, 0);

    // val chain
    gemm_mlp_l(hh, hl, HH, rwh + O_R2W0, rwl + O_R2W0, 512,
               ROWS, 128, HH, r2b[0], 1, false, nullptr, nullptr, t0h, t0l, 128, 1);
    gemm_mlp_l(t0h, t0l, 128, rwh + O_R2W1, rwl + O_R2W1, 128,
               ROWS, 256, 128, r2b[1], 1, false, nullptr, nullptr, t1h, t1l, 256, 1);
    gemm_mlp_l(t1h, t1l, 256, rwh + O_R2W2, rwl + O_R2W2, 256,
               ROWS, 128, 256, r2b[2], 1, false, nullptr, nullptr, t0h, t0l, 128, 1);
    gemm_mlp_l(t0h, t0l, 128, rwh + O_R2W3, rwl + O_R2W3, 128,
               ROWS, TGT, 128, r2b[3], 0, false, nullptr, val, nullptr, nullptr, TGT, 0);

    reduce_kernel<<<BQ, 128>>>(gate, val, mask, out);
}

// round 16
// speedup vs baseline: 1.6585x; 1.0636x over previous
#include <cuda_runtime.h>
#include <cuda_bf16.h>
#include <cstdint>

#define BQ   64
#define NN   128
#define FIN  128
#define HH   512
#define MSGD 512
#define LL   4
#define ROWS (BQ*NN)
#define TGT  12

typedef __nv_bfloat16 bf16;

// ---------------- scratch ----------------
__device__ float g_h    [ROWS*HH];
__device__ float g_hproj[BQ*LL*NN*MSGD];
__device__ float g_gigh [2*ROWS*3*HH];     // gi then gh
__device__ float g_mask [ROWS];
__device__ float g_t0f  [ROWS*128];
__device__ float g_gv   [2*ROWS*TGT];      // gate then val
// bf16 hi/lo planes — m and h POOLED so batched pointer deltas are valid
__device__ bf16 g_xh[2*ROWS*512], g_xl[2*ROWS*512];   // [0]=m planes, [1]=h planes
__device__ bf16 g_hinh[ROWS*FIN], g_hinl[ROWS*FIN];
__device__ bf16 g_p0h[2*ROWS*128], g_p0l[2*ROWS*128];
__device__ bf16 g_p1h[2*ROWS*256], g_p1l[2*ROWS*256];
__device__ bf16 g_ATh[LL*HH*MSGD],  g_ATl[LL*HH*MSGD];
__device__ bf16 g_Wh[2*3*HH*MSGD],  g_Wl[2*3*HH*MSGD];   // Wih then Whh planes
__device__ bf16 g_rwh[512*1024],    g_rwl[512*1024];

// ---------------- helpers ----------------
__device__ __forceinline__ void bsplit1(float x, uint16_t& h, uint16_t& l) {
    bf16 b = __float2bfloat16_rn(x);
    h = __bfloat16_as_ushort(b);
    l = __bfloat16_as_ushort(__float2bfloat16_rn(x - __bfloat162float(b)));
}
__device__ __forceinline__ void mma_bf16(float* d, const uint32_t* a, const uint32_t* b) {
    asm volatile(
        "mma.sync.aligned.m16n8k16.row.col.f32.bf16.bf16.f32 "
        "{%0,%1,%2,%3}, {%4,%5,%6,%7}, {%8,%9}, {%0,%1,%2,%3};\n"
        : "+f"(d[0]), "+f"(d[1]), "+f"(d[2]), "+f"(d[3])
        : "r"(a[0]), "r"(a[1]), "r"(a[2]), "r"(a[3]), "r"(b[0]), "r"(b[1]));
}
__device__ __forceinline__ void ldsm_x4(uint32_t& r0, uint32_t& r1, uint32_t& r2, uint32_t& r3,
                                        uint32_t addr) {
    asm volatile("ldmatrix.sync.aligned.m8n8.x4.shared.b16 {%0,%1,%2,%3}, [%4];"
                 : "=r"(r0), "=r"(r1), "=r"(r2), "=r"(r3) : "r"(addr));
}
__device__ __forceinline__ void cp16(uint32_t dst, const void* src) {
    asm volatile("cp.async.cg.shared.global [%0], [%1], 16;" :: "r"(dst), "l"(src));
}
__device__ __forceinline__ void cp16z(uint32_t dst, const void* src, int srcsize) {
    asm volatile("cp.async.cg.shared.global [%0], [%1], 16, %2;" :: "r"(dst), "l"(src), "r"(srcsize));
}
#define CP_COMMIT() asm volatile("cp.async.commit_group;")
#define CP_WAIT1()  asm volatile("cp.async.wait_group 1;")

#define ROWB 48
#define PIPE 3

// ================= BIG kernel =================
#define PLB   (128 * ROWB)
#define STGB  (4 * PLB)
#define BIG_SMEM_BYTES (PIPE * STGB)

__global__ void __launch_bounds__(256, 2)
tgemm_big(const bf16* __restrict__ Ah_, const bf16* __restrict__ Al_, int lda,
          const bf16* __restrict__ Bh_, const bf16* __restrict__ Bl_, int ldb,
          float* __restrict__ C, int ldc,
          int K, const float* __restrict__ bias, long long biasHi,
          int dv,
          long long aHi, long long aLo,
          long long bHi, long long bLo,
          long long cHi, long long cLo)
{
    extern __shared__ char smc[];

    int z = blockIdx.z;
    int zh = z / dv, zl = z % dv;
    Ah_ += zh*aHi + zl*aLo;  Al_ += zh*aHi + zl*aLo;
    Bh_ += zh*bHi + zl*bLo;  Bl_ += zh*bHi + zl*bLo;
    C   += zh*cHi + zl*cLo;
    if (bias) bias += zh * biasHi;

    int tid  = threadIdx.x;
    int lane = tid & 31;
    int wid  = tid >> 5;
    int gid  = lane >> 2;
    int tig  = lane & 3;
    int quad = lane >> 3;
    int rowin= lane & 7;
    int wm   = (wid & 3) * 32;
    int wn   = (wid >> 2) * 64;
    int m0   = blockIdx.y * 128;
    int n0   = blockIdx.x * 128;

    uint32_t sbase = (uint32_t)__cvta_generic_to_shared(smc);
    int aoff = ((quad & 1) * 8 + rowin) * ROWB + ((quad >> 1) * 16);
    int boff = ((quad >> 1) * 8 + rowin) * ROWB + ((quad & 1) * 16);

    int cr = tid >> 1;
    int cc = (tid & 1) * 16;
    const char* baseAh = (const char*)(Ah_ + (size_t)(m0 + cr) * lda) + cc;
    const char* baseAl = (const char*)(Al_ + (size_t)(m0 + cr) * lda) + cc;
    const char* baseBh = (const char*)(Bh_ + (size_t)(n0 + cr) * ldb) + cc;
    const char* baseBl = (const char*)(Bl_ + (size_t)(n0 + cr) * ldb) + cc;
    uint32_t dstA = sbase + cr * ROWB + cc;

    auto cpstage = [&](int s, int k0) {
        uint32_t d = dstA + s * STGB;
        size_t go = (size_t)k0 * 2;
        cp16(d,         baseAh + go);
        cp16(d + PLB,   baseAl + go);
        cp16(d + 2*PLB, baseBh + go);
        cp16(d + 3*PLB, baseBl + go);
    };

    float acc[2][8][4];
#pragma unroll
    for (int mt = 0; mt < 2; mt++)
#pragma unroll
        for (int nt = 0; nt < 8; nt++)
#pragma unroll
            for (int q = 0; q < 4; q++) acc[mt][nt][q] = 0.f;

#pragma unroll
    for (int s = 0; s < PIPE - 1; s++) {
        cpstage(s, s * 16);
        CP_COMMIT();
    }
    CP_WAIT1();
    __syncthreads();

    int rd = 0, wr = PIPE - 1;
    for (int k0 = 0; k0 < K; k0 += 16) {
        int pk = k0 + (PIPE - 1) * 16;
        if (pk < K) cpstage(wr, pk);
        CP_COMMIT();

        uint32_t bb  = sbase + rd * STGB;
        uint32_t ahp = bb + wm * ROWB + aoff;
        uint32_t alp = ahp + PLB;
        uint32_t bhp = bb + 2*PLB + wn * ROWB + boff;
        uint32_t blp = bhp + PLB;

        uint32_t afh[2][4], afl[2][4], bfh[8][2], bfl[8][2];
        ldsm_x4(afh[0][0], afh[0][1], afh[0][2], afh[0][3], ahp);
        ldsm_x4(afh[1][0], afh[1][1], afh[1][2], afh[1][3], ahp + 16 * ROWB);
        ldsm_x4(afl[0][0], afl[0][1], afl[0][2], afl[0][3], alp);
        ldsm_x4(afl[1][0], afl[1][1], afl[1][2], afl[1][3], alp + 16 * ROWB);
#pragma unroll
        for (int p = 0; p < 4; p++) {
            ldsm_x4(bfh[2*p][0], bfh[2*p][1], bfh[2*p+1][0], bfh[2*p+1][1], bhp + p * 16 * ROWB);
            ldsm_x4(bfl[2*p][0], bfl[2*p][1], bfl[2*p+1][0], bfl[2*p+1][1], blp + p * 16 * ROWB);
        }
#pragma unroll
        for (int mt = 0; mt < 2; mt++)
#pragma unroll
            for (int nt = 0; nt < 8; nt++) {
                mma_bf16(acc[mt][nt], afl[mt], bfh[nt]);
                mma_bf16(acc[mt][nt], afh[mt], bfl[nt]);
                mma_bf16(acc[mt][nt], afh[mt], bfh[nt]);
            }
        CP_WAIT1();
        __syncthreads();
        rd = (rd + 1) % PIPE;
        wr = (wr + 1) % PIPE;
    }

#pragma unroll
    for (int mt = 0; mt < 2; mt++) {
#pragma unroll
        for (int nt = 0; nt < 8; nt++) {
            int row = m0 + wm + mt * 16 + gid;
            int col = n0 + wn + nt * 8 + tig * 2;
#pragma unroll
            for (int half = 0; half < 2; half++) {
                int r = row + half * 8;
                float v0 = acc[mt][nt][half * 2 + 0];
                float v1 = acc[mt][nt][half * 2 + 1];
                size_t idx = (size_t)r * ldc + col;
                if (bias) {
                    v0 += __ldg(bias + col);
                    v1 += __ldg(bias + col + 1);
                }
                *(float2*)(C + idx) = make_float2(v0, v1);
            }
        }
    }
}

// ================= MLP kernel (batched via blockIdx.z + pooled-array deltas) =================
#define PLA_M  (128 * ROWB)
#define PLB_M  (64 * ROWB)
#define STG_M  (2 * PLA_M + 2 * PLB_M)
#define MLP_SMEM (PIPE * STG_M)

template<bool ACC>
__global__ void __launch_bounds__(256, 2)
tgemm_mlp(const bf16* __restrict__ Ah_, const bf16* __restrict__ Al_, int lda,
          const bf16* __restrict__ Bh_, const bf16* __restrict__ Bl_, int ldb,
          int N, int K,
          const float* __restrict__ bias, long long biasHi, int actA, int actB,
          const float* __restrict__ Cacc,
          float* __restrict__ Cf, bf16* __restrict__ Ch, bf16* __restrict__ Cl,
          int ldc, int outmode,
          long long aHi, long long bHi, long long cHi)
{
    extern __shared__ char smc[];

    int zh = blockIdx.z;
    Ah_ += zh*aHi;  Al_ += zh*aHi;
    Bh_ += zh*bHi;  Bl_ += zh*bHi;
    if (bias) bias += zh * biasHi;
    int act = zh ? actB : actA;

    int tid  = threadIdx.x;
    int lane = tid & 31;
    int wid  = tid >> 5;
    int gid  = lane >> 2;
    int tig  = lane & 3;
    int quad = lane >> 3;
    int rowin= lane & 7;
    int wm   = (wid & 3) * 32;
    int wn   = (wid >> 2) * 32;
    int m0   = blockIdx.y * 128;
    int n0   = blockIdx.x * 64;

    uint32_t sbase = (uint32_t)__cvta_generic_to_shared(smc);
    int aoff = ((quad & 1) * 8 + rowin) * ROWB + ((quad >> 1) * 16);
    int boff = ((quad >> 1) * 8 + rowin) * ROWB + ((quad & 1) * 16);

    int cr = tid >> 1;
    int cc = (tid & 1) * 16;
    const char* baseAh = (const char*)(Ah_ + (size_t)(m0 + cr) * lda) + cc;
    const char* baseAl = (const char*)(Al_ + (size_t)(m0 + cr) * lda) + cc;
    int brow = cr & 63;
    int bok  = (cr < 64) && (n0 + brow < N);
    int bsz  = bok ? 16 : 0;
    int brc  = bok ? (n0 + brow) : 0;
    const char* baseBh = (const char*)(Bh_ + (size_t)brc * ldb) + cc;
    const char* baseBl = (const char*)(Bl_ + (size_t)brc * ldb) + cc;
    uint32_t dstA = sbase + cr * ROWB + cc;
    uint32_t dstB = sbase + 2*PLA_M + brow * ROWB + cc;

    auto cpstage = [&](int s, int k0) {
        size_t go = (size_t)k0 * 2;
        cp16(dstA + s * STG_M,         baseAh + go);
        cp16(dstA + s * STG_M + PLA_M, baseAl + go);
        if (cr < 64) {
            cp16z(dstB + s * STG_M,         baseBh + go, bsz);
            cp16z(dstB + s * STG_M + PLB_M, baseBl + go, bsz);
        }
    };

    float acc[2][4][4];
#pragma unroll
    for (int mt = 0; mt < 2; mt++)
#pragma unroll
        for (int nt = 0; nt < 4; nt++)
#pragma unroll
            for (int q = 0; q < 4; q++) acc[mt][nt][q] = 0.f;

#pragma unroll
    for (int s = 0; s < PIPE - 1; s++) {
        if (s * 16 < K) cpstage(s, s * 16);
        CP_COMMIT();
    }
    CP_WAIT1();
    __syncthreads();

    int rd = 0, wr = PIPE - 1;
    for (int k0 = 0; k0 < K; k0 += 16) {
        int pk = k0 + (PIPE - 1) * 16;
        if (pk < K) cpstage(wr, pk);
        CP_COMMIT();

        uint32_t bb  = sbase + rd * STG_M;
        uint32_t ahp = bb + wm * ROWB + aoff;
        uint32_t alp = ahp + PLA_M;
        uint32_t bhp = bb + 2*PLA_M + wn * ROWB + boff;
        uint32_t blp = bhp + PLB_M;

        uint32_t afh[2][4], afl[2][4], bfh[4][2], bfl[4][2];
        ldsm_x4(afh[0][0], afh[0][1], afh[0][2], afh[0][3], ahp);
        ldsm_x4(afh[1][0], afh[1][1], afh[1][2], afh[1][3], ahp + 16 * ROWB);
        ldsm_x4(afl[0][0], afl[0][1], afl[0][2], afl[0][3], alp);
        ldsm_x4(afl[1][0], afl[1][1], afl[1][2], afl[1][3], alp + 16 * ROWB);
#pragma unroll
        for (int p = 0; p < 2; p++) {
            ldsm_x4(bfh[2*p][0], bfh[2*p][1], bfh[2*p+1][0], bfh[2*p+1][1], bhp + p * 16 * ROWB);
            ldsm_x4(bfl[2*p][0], bfl[2*p][1], bfl[2*p+1][0], bfl[2*p+1][1], blp + p * 16 * ROWB);
        }
#pragma unroll
        for (int mt = 0; mt < 2; mt++)
#pragma unroll
            for (int nt = 0; nt < 4; nt++) {
                mma_bf16(acc[mt][nt], afl[mt], bfh[nt]);
                mma_bf16(acc[mt][nt], afh[mt], bfl[nt]);
                mma_bf16(acc[mt][nt], afh[mt], bfh[nt]);
            }
        CP_WAIT1();
        __syncthreads();
        rd = (rd + 1) % PIPE;
        wr = (wr + 1) % PIPE;
    }

#pragma unroll
    for (int mt = 0; mt < 2; mt++) {
#pragma unroll
        for (int nt = 0; nt < 4; nt++) {
            int row = m0 + wm + mt * 16 + gid;
            int col = n0 + wn + nt * 8 + tig * 2;
            if (col < N) {
#pragma unroll
                for (int half = 0; half < 2; half++) {
                    int r = row + half * 8;
                    float v0 = acc[mt][nt][half * 2 + 0];
                    float v1 = acc[mt][nt][half * 2 + 1];
                    size_t idx = (size_t)r * ldc + col;
                    if (ACC) {
                        float2 old = *(const float2*)(Cacc + idx);
                        v0 += old.x; v1 += old.y;
                    }
                    if (bias) {
                        v0 += __ldg(bias + col);
                        v1 += __ldg(bias + col + 1);
                    }
                    if (act == 1) { v0 = fmaxf(v0, 0.f); v1 = fmaxf(v1, 0.f); }
                    else if (act == 2) {
                        v0 = 1.f / (1.f + __expf(-v0));
                        v1 = 1.f / (1.f + __expf(-v1));
                    }
                    size_t oidx = idx + (size_t)zh * cHi;
                    if (outmode == 0) {
                        *(float2*)(Cf + oidx) = make_float2(v0, v1);
                    } else {
                        uint16_t h0, l0, h1, l1;
                        bsplit1(v0, h0, l0);
                        bsplit1(v1, h1, l1);
                        *(uint32_t*)(Ch + oidx) = (uint32_t)h0 | ((uint32_t)h1 << 16);
                        *(uint32_t*)(Cl + oidx) = (uint32_t)l0 | ((uint32_t)l1 << 16);
                    }
                }
            }
        }
    }
}

// ---------------- fused conversion ----------------
#define NSEG 10
struct ConvArgs {
    const float* src[NSEG];
    bf16* dh[NSEG];
    bf16* dl[NSEG];
    int prefix[NSEG + 1];
};
__global__ void convert_all_kernel(ConvArgs a)
{
    int i = blockIdx.x * 256 + threadIdx.x;
    if (i >= a.prefix[NSEG]) return;
    int s = 0;
    while (i >= a.prefix[s + 1]) s++;
    int j = i - a.prefix[s];
    float x = a.src[s][j];
    bf16 h = __float2bfloat16_rn(x);
    a.dh[s][j] = h;
    a.dl[s][j] = __float2bfloat16_rn(x - __bfloat162float(h));
}

__global__ void transposeA_kernel(const float* __restrict__ Amat,
                                  bf16* __restrict__ ATh, bf16* __restrict__ ATl)
{
    __shared__ float tile[32][33];
    int l = blockIdx.z;
    int kb = blockIdx.x * 32;
    int mb = blockIdx.y * 32;
    const float* src = Amat + (size_t)l * HH * MSGD;
    int tx = threadIdx.x, ty = threadIdx.y;
#pragma unroll
    for (int i = 0; i < 4; i++)
        tile[ty + i * 8][tx] = src[(size_t)(kb + ty + i * 8) * MSGD + mb + tx];
    __syncthreads();
#pragma unroll
    for (int i = 0; i < 4; i++) {
        int m = mb + ty + i * 8;
        float x = tile[tx][ty + i * 8];
        bf16 h = __float2bfloat16_rn(x);
        size_t o = (size_t)l * HH * MSGD + (size_t)m * HH + kb + tx;
        ATh[o] = h;
        ATl[o] = __float2bfloat16_rn(x - __bfloat162float(h));
    }
}

// ---------------- elementwise ----------------
__global__ void init_kernel(const float* __restrict__ h_in,
                            float* __restrict__ h, float* __restrict__ mask,
                            bf16* __restrict__ hh, bf16* __restrict__ hl,
                            bf16* __restrict__ hinh, bf16* __restrict__ hinl)
{
    int row = blockIdx.x;
    int t = threadIdx.x;
    float v = h_in[(size_t)row * FIN + t];
    float s = fabsf(v);
#pragma unroll
    for (int o = 16; o; o >>= 1) s += __shfl_xor_sync(0xffffffffu, s, o);
    __shared__ float ws[4];
    if ((t & 31) == 0) ws[t >> 5] = s;
    __syncthreads();
    if (t == 0) {
        float tot = ws[0] + ws[1] + ws[2] + ws[3];
        mask[row] = (tot > 0.f) ? 1.f : 0.f;
    }
    size_t rb = (size_t)row * HH;
    h[rb + t] = v;
    h[rb + t + 128] = 0.f; h[rb + t + 256] = 0.f; h[rb + t + 384] = 0.f;
    uint16_t hi, lo;
    bsplit1(v, hi, lo);
    hh[rb + t] = __ushort_as_bfloat16(hi);
    hl[rb + t] = __ushort_as_bfloat16(lo);
    bf16 z = __float2bfloat16_rn(0.f);
    hh[rb + t + 128] = z; hh[rb + t + 256] = z; hh[rb + t + 384] = z;
    hl[rb + t + 128] = z; hl[rb + t + 256] = z; hl[rb + t + 384] = z;
    hinh[(size_t)row * FIN + t] = __ushort_as_bfloat16(hi);
    hinl[(size_t)row * FIN + t] = __ushort_as_bfloat16(lo);
}

__global__ void agg_kernel(const float* __restrict__ e,
                           const float* __restrict__ hproj,
                           bf16* __restrict__ mh, bf16* __restrict__ ml)
{
    int row = blockIdx.x;
    int b = row >> 7;
    int t = threadIdx.x;
    __shared__ int cnt;
    __shared__ int widx[NN];
    __shared__ int wlab[NN];
    if (t == 0) cnt = 0;
    __syncthreads();
    float ev = e[(size_t)row * NN + t];
    int lab = (int)(ev + 0.5f);
    if (lab >= 1) {
        int p = atomicAdd(&cnt, 1);
        widx[p] = t;
        wlab[p] = lab - 1;
    }
    __syncthreads();
    float a0 = 0.f, a1 = 0.f, a2 = 0.f, a3 = 0.f;
    int n = cnt;
    const float* hb = hproj + (size_t)b * LL * NN * MSGD;
    for (int i = 0; i < n; i++) {
        const float* src = hb + ((size_t)wlab[i] * NN + widx[i]) * MSGD;
        a0 += __ldg(src + t);
        a1 += __ldg(src + t + 128);
        a2 += __ldg(src + t + 256);
        a3 += __ldg(src + t + 384);
    }
    size_t o = (size_t)row * MSGD;
    float vals[4] = {a0, a1, a2, a3};
#pragma unroll
    for (int j = 0; j < 4; j++) {
        uint16_t hi, lo;
        bsplit1(vals[j], hi, lo);
        mh[o + t + j * 128] = __ushort_as_bfloat16(hi);
        ml[o + t + j * 128] = __ushort_as_bfloat16(lo);
    }
}

__global__ void gru_kernel(float* __restrict__ h,
                           const float* __restrict__ gigh,
                           const float* __restrict__ mask,
                           bf16* __restrict__ hh, bf16* __restrict__ hl)
{
    int row = blockIdx.x;
    int t = threadIdx.x;
    float mk = mask[row];
    const float* gir = gigh + (size_t)row * 3 * HH;
    const float* ghr = gigh + (size_t)ROWS * 3 * HH + (size_t)row * 3 * HH;
    float* hr = h + (size_t)row * HH;
    size_t rb = (size_t)row * HH;
#pragma unroll
    for (int j = 0; j < 4; j++) {
        int idx = t + j * 128;
        float ir = gir[idx], iz = gir[idx + HH], in_ = gir[idx + 2 * HH];
        float hrv = ghr[idx], hz = ghr[idx + HH], hn = ghr[idx + 2 * HH];
        float r  = 1.f / (1.f + __expf(-(ir + hrv)));
        float z  = 1.f / (1.f + __expf(-(iz + hz)));
        float nn = tanhf(in_ + r * hn);
        float ho = hr[idx];
        float v = ((1.f - z) * nn + z * ho) * mk;
        hr[idx] = v;
        uint16_t hi, lo;
        bsplit1(v, hi, lo);
        hh[rb + idx] = __ushort_as_bfloat16(hi);
        hl[rb + idx] = __ushort_as_bfloat16(lo);
    }
}

__global__ void reduce_kernel(const float* __restrict__ gv,
                              const float* __restrict__ mask,
                              float* __restrict__ out)
{
    __shared__ float sm[TGT][NN];
    int b = blockIdx.x;
    int t = threadIdx.x;
    int row = b * NN + t;
    float mk = mask[row];
    const float* gate = gv;
    const float* val  = gv + (size_t)ROWS * TGT;
#pragma unroll
    for (int j = 0; j < TGT; j++)
        sm[j][t] = gate[(size_t)row * TGT + j] * val[(size_t)row * TGT + j] * mk;
    __syncthreads();
    for (int s = 64; s > 0; s >>= 1) {
        if (t < s) {
#pragma unroll
            for (int j = 0; j < TGT; j++) sm[j][t] += sm[j][t + s];
        }
        __syncthreads();
    }
    if (t < TGT) out[b * TGT + t] = sm[t][0];
}

// ---------------- host ----------------
static void gemm_big_l(const bf16* Ah, const bf16* Al, int lda,
                       const bf16* Bh, const bf16* Bl, int ldb,
                       float* C, int ldc, int M, int N, int K,
                       const float* bias, long long biasHi,
                       int batches, int dv,
                       long long aHi, long long aLo,
                       long long bHi, long long bLo,
                       long long cHi, long long cLo)
{
    dim3 grid(N / 128, M / 128, batches);
    tgemm_big<<<grid, 256, BIG_SMEM_BYTES>>>(Ah, Al, lda, Bh, Bl, ldb, C, ldc, K, bias, biasHi,
                                             dv, aHi, aLo, bHi, bLo, cHi, cLo);
}

static void gemm_mlp_l(const bf16* Ah, const bf16* Al, int lda,
                       const bf16* Bh, const bf16* Bl, int ldb,
                       int M, int N, int K,
                       const float* bias, long long biasHi, int actA, int actB, bool acc,
                       const float* Cacc, float* Cf, bf16* Ch, bf16* Cl, int ldc, int outmode,
                       int zN, long long aHi, long long bHi, long long cHi)
{
    dim3 grid((N + 63) / 64, M / 128, zN);
    if (acc) tgemm_mlp<true ><<<grid, 256, MLP_SMEM>>>(Ah, Al, lda, Bh, Bl, ldb, N, K, bias, biasHi, actA, actB, Cacc, Cf, Ch, Cl, ldc, outmode, aHi, bHi, cHi);
    else     tgemm_mlp<false><<<grid, 256, MLP_SMEM>>>(Ah, Al, lda, Bh, Bl, ldb, N, K, bias, biasHi, actA, actB, Cacc, Cf, Ch, Cl, ldc, outmode, aHi, bHi, cHi);
}

extern "C" void kernel_launch(void* const* d_in, const int* in_sizes, int n_in,
                              void* d_out, int out_size)
{
    const float* h_in  = (const float*)d_in[1];
    const float* e     = (const float*)d_in[2];
    const float* Amat  = (const float*)d_in[3];
    const float* Wih   = (const float*)d_in[4];
    const float* Whh   = (const float*)d_in[5];
    const float* bih   = (const float*)d_in[6];
    const float* bhh   = (const float*)d_in[7];

    cudaFuncSetAttribute(tgemm_big, cudaFuncAttributeMaxDynamicSharedMemorySize, BIG_SMEM_BYTES);
    cudaFuncSetAttribute(tgemm_mlp<true >, cudaFuncAttributeMaxDynamicSharedMemorySize, MLP_SMEM);
    cudaFuncSetAttribute(tgemm_mlp<false>, cudaFuncAttributeMaxDynamicSharedMemorySize, MLP_SMEM);

    const float *r1W[4], *r1b[4], *r2W[4], *r2b[4];
    if (in_sizes[10] == 65536) {
        for (int i = 0; i < 4; i++) {
            r1W[i] = (const float*)d_in[8 + 4 * i];
            r1b[i] = (const float*)d_in[9 + 4 * i];
            r2W[i] = (const float*)d_in[10 + 4 * i];
            r2b[i] = (const float*)d_in[11 + 4 * i];
        }
    } else {
        for (int i = 0; i < 4; i++) {
            r1W[i] = (const float*)d_in[8 + 2 * i];
            r1b[i] = (const float*)d_in[9 + 2 * i];
            r2W[i] = (const float*)d_in[16 + 2 * i];
            r2b[i] = (const float*)d_in[17 + 2 * i];
        }
    }
    float* out = (float*)d_out;

    float *h_, *hproj, *gigh, *mask, *t0f, *gv;
    cudaGetSymbolAddress((void**)&h_,    g_h);
    cudaGetSymbolAddress((void**)&hproj, g_hproj);
    cudaGetSymbolAddress((void**)&gigh,  g_gigh);
    cudaGetSymbolAddress((void**)&mask,  g_mask);
    cudaGetSymbolAddress((void**)&t0f,   g_t0f);
    cudaGetSymbolAddress((void**)&gv,    g_gv);

    bf16 *xh, *xl, *hinh, *hinl, *p0h, *p0l, *p1h, *p1l;
    bf16 *ATh, *ATl, *Wh, *Wl, *rwh, *rwl;
    cudaGetSymbolAddress((void**)&xh,   g_xh);   cudaGetSymbolAddress((void**)&xl,   g_xl);
    cudaGetSymbolAddress((void**)&hinh, g_hinh); cudaGetSymbolAddress((void**)&hinl, g_hinl);
    cudaGetSymbolAddress((void**)&p0h,  g_p0h);  cudaGetSymbolAddress((void**)&p0l,  g_p0l);
    cudaGetSymbolAddress((void**)&p1h,  g_p1h);  cudaGetSymbolAddress((void**)&p1l,  g_p1l);
    cudaGetSymbolAddress((void**)&ATh,  g_ATh);  cudaGetSymbolAddress((void**)&ATl,  g_ATl);
    cudaGetSymbolAddress((void**)&Wh,   g_Wh);   cudaGetSymbolAddress((void**)&Wl,   g_Wl);
    cudaGetSymbolAddress((void**)&rwh,  g_rwh);  cudaGetSymbolAddress((void**)&rwl,  g_rwl);

    // pooled activation planes: m at 0, h at ROWS*512
    const long long MPOOL = (long long)ROWS * 512;
    bf16 *mh = xh,        *ml = xl;
    bf16 *hh = xh + MPOOL,*hl = xl + MPOOL;

    const int O_R1W0 = 0;
    const int O_R1W1 = O_R1W0 + 128 * 1024;
    const int O_R1W2 = O_R1W1 + 256 * 128;
    const int O_R1W3 = O_R1W2 + 128 * 256;
    const int O_R2W0 = O_R1W3 + 12 * 128;
    const int O_R2W1 = O_R2W0 + 128 * 512;
    const int O_R2W2 = O_R2W1 + 256 * 128;
    const int O_R2W3 = O_R2W2 + 128 * 256;

    {
        ConvArgs a;
        const float* srcs[NSEG] = {Wih, Whh, r1W[0], r1W[1], r1W[2], r1W[3], r2W[0], r2W[1], r2W[2], r2W[3]};
        bf16* dhs[NSEG] = {Wh, Wh + 3*HH*MSGD, rwh + O_R1W0, rwh + O_R1W1, rwh + O_R1W2, rwh + O_R1W3,
                           rwh + O_R2W0, rwh + O_R2W1, rwh + O_R2W2, rwh + O_R2W3};
        bf16* dls[NSEG] = {Wl, Wl + 3*HH*MSGD, rwl + O_R1W0, rwl + O_R1W1, rwl + O_R1W2, rwl + O_R1W3,
                           rwl + O_R2W0, rwl + O_R2W1, rwl + O_R2W2, rwl + O_R2W3};
        int ns[NSEG] = {3*HH*MSGD, 3*HH*HH, 128*1024, 256*128, 128*256, 12*128,
                        128*512, 256*128, 128*256, 12*128};
        int pf = 0;
        for (int i = 0; i < NSEG; i++) {
            a.src[i] = srcs[i]; a.dh[i] = dhs[i]; a.dl[i] = dls[i];
            a.prefix[i] = pf; pf += ns[i];
        }
        a.prefix[NSEG] = pf;
        convert_all_kernel<<<(pf + 255) / 256, 256>>>(a);
    }
    {
        dim3 tg(HH / 32, MSGD / 32, LL);
        transposeA_kernel<<<tg, dim3(32, 8)>>>(Amat, ATh, ATl);
    }

    init_kernel<<<ROWS, 128>>>(h_in, h_, mask, hh, hl, hinh, hinl);

    for (int step = 0; step < 4; step++) {
        gemm_big_l(hh, hl, HH, ATh, ATl, HH, hproj, MSGD,
                   NN, MSGD, HH, nullptr, 0,
                   BQ * LL, LL,
                   (long long)NN * HH, 0,
                   0, (long long)HH * MSGD,
                   (long long)LL * NN * MSGD, (long long)NN * MSGD);

        agg_kernel<<<ROWS, 128>>>(e, hproj, mh, ml);

        // batched gi|gh: z=0 -> (m planes, Wih, bih), z=1 -> (h planes, Whh, bhh)
        // aHi = MPOOL valid for BOTH hi and lo pools (pooled array).
        gemm_big_l(mh, ml, MSGD, Wh, Wl, MSGD, gigh, 3 * HH,
                   ROWS, 3 * HH, MSGD, bih, (long long)(bhh - bih),
                   2, 1,
                   MPOOL, 0,
                   (long long)(3 * HH * MSGD), 0,
                   (long long)ROWS * 3 * HH, 0);

        gru_kernel<<<ROWS, 128>>>(h_, gigh, mask, hh, hl);
    }

    const long long PA0 = (long long)ROWS * 128;
    const long long PA1 = (long long)ROWS * 256;

    // gate L0 (two parts) + val L0 (unbatched)
    gemm_mlp_l(hh, hl, HH, rwh + O_R1W0, rwl + O_R1W0, 1024,
               ROWS, 128, HH, nullptr, 0, 0, 0, false, nullptr, t0f, nullptr, nullptr, 128, 0,
               1, 0, 0, 0);
    gemm_mlp_l(hinh, hinl, FIN, rwh + O_R1W0 + 512, rwl + O_R1W0 + 512, 1024,
               ROWS, 128, FIN, r1b[0], 0, 1, 1, true, t0f, nullptr, p0h, p0l, 128, 1,
               1, 0, 0, 0);
    gemm_mlp_l(hh, hl, HH, rwh + O_R2W0, rwl + O_R2W0, 512,
               ROWS, 128, HH, r2b[0], 0, 1, 1, false, nullptr, nullptr, p0h + PA0, p0l + PA0, 128, 1,
               1, 0, 0, 0);

    // batched L1: (p0 gate|val) @ (r1W1|r2W1) -> p1
    gemm_mlp_l(p0h, p0l, 128, rwh + O_R1W1, rwl + O_R1W1, 128,
               ROWS, 256, 128, r1b[1], (long long)(r2b[1] - r1b[1]), 1, 1, false,
               nullptr, nullptr, p1h, p1l, 256, 1,
               2, PA0, (long long)(O_R2W1 - O_R1W1), PA1);
    // batched L2: p1 -> p0
    gemm_mlp_l(p1h, p1l, 256, rwh + O_R1W2, rwl + O_R1W2, 256,
               ROWS, 128, 256, r1b[2], (long long)(r2b[2] - r1b[2]), 1, 1, false,
               nullptr, nullptr, p0h, p0l, 128, 1,
               2, PA1, (long long)(O_R2W2 - O_R1W2), PA0);
    // batched L3: p0 -> gv (gate sigmoid | val none)
    gemm_mlp_l(p0h, p0l, 128, rwh + O_R1W3, rwl + O_R1W3, 128,
               ROWS, TGT, 128, r1b[3], (long long)(r2b[3] - r1b[3]), 2, 0, false,
               nullptr, gv, nullptr, nullptr, TGT, 0,
               2, PA0, (long long)(O_R2W3 - O_R1W3), (long long)ROWS * TGT);

    reduce_kernel<<<BQ, 128>>>(gv, mask, out);
}